// round 12
// baseline (speedup 1.0000x reference)
#include <cuda_runtime.h>
#include <math.h>
#include <stdint.h>

// ---------------- problem constants ----------------
#define B_   8
#define C_   128
#define HW_  4096
#define NKV_ 256
#define RPE_N 16129     // 127*127

typedef unsigned long long ull;

// ---------------- helpers ----------------
__device__ __forceinline__ float ex2f(float x) {
    float r;
    asm("ex2.approx.f32 %0, %1;" : "=f"(r) : "f"(x));
    return r;
}
__device__ __forceinline__ float tf32r(float x) {
    uint32_t u;
    asm("cvt.rna.tf32.f32 %0, %1;" : "=r"(u) : "f"(x));
    return __uint_as_float(u);
}
__device__ __forceinline__ void mma_tf32(float d[4],
    uint32_t a0, uint32_t a1, uint32_t a2, uint32_t a3,
    uint32_t b0, uint32_t b1)
{
    asm volatile(
        "mma.sync.aligned.m16n8k8.row.col.f32.tf32.tf32.f32 "
        "{%0,%1,%2,%3}, {%4,%5,%6,%7}, {%8,%9}, {%0,%1,%2,%3};"
        : "+f"(d[0]), "+f"(d[1]), "+f"(d[2]), "+f"(d[3])
        : "r"(a0), "r"(a1), "r"(a2), "r"(a3), "r"(b0), "r"(b1));
}
#define FU(x) __float_as_uint(x)

// ---------------- device scratch ----------------
__device__ float g_q  [B_ * C_ * HW_];
__device__ float g_ao [B_ * C_ * HW_];
__device__ float g_pos[16 * NKV_ * 2];
__device__ float g_xs [B_ * C_ * NKV_];
__device__ float g_k  [B_ * C_ * NKV_];
__device__ float g_v  [B_ * C_ * NKV_];

// ---------------- tf32 mma GEMM: Y[128, 256-tile] = A[128x128] * X ----------------
#define GT_FLOATS (16896 + 33792)   // 50688 floats = 202752 B

__device__ __forceinline__ void gemm_tf32_tile(
    const float* __restrict__ A, const float* __restrict__ Xb,
    float* __restrict__ Yb, int ld, int rnd)
{
    extern __shared__ float sm[];
    float* a_sm = sm;
    float* b_sm = sm + 16896;
    int tid = threadIdx.x;

    for (int i = tid; i < 4096; i += 1024) {
        int m = i >> 5, k0 = (i & 31) * 4;
        float4 v = *(const float4*)(A + m * 128 + k0);
        float* d = a_sm + m * 132 + k0;
        d[0] = tf32r(v.x); d[1] = tf32r(v.y); d[2] = tf32r(v.z); d[3] = tf32r(v.w);
    }
    for (int i = tid; i < 8192; i += 1024) {
        int k = i >> 6, n0 = (i & 63) * 4;
        float4 v = *(const float4*)(Xb + (size_t)k * ld + n0);
        float* d = b_sm + k * 264 + n0;
        d[0] = tf32r(v.x); d[1] = tf32r(v.y); d[2] = tf32r(v.z); d[3] = tf32r(v.w);
    }
    __syncthreads();

    int lane = tid & 31, w = tid >> 5;
    int r4 = lane >> 2, c4 = lane & 3;
    int mt = (w >> 3) * 32;
    int nt = (w & 7) * 32;

    float d[2][4][4];
#pragma unroll
    for (int s = 0; s < 2; s++)
#pragma unroll
        for (int nb = 0; nb < 4; nb++)
#pragma unroll
            for (int j = 0; j < 4; j++) d[s][nb][j] = 0.f;

#pragma unroll
    for (int ks = 0; ks < 16; ks++) {
        int kc = ks * 8 + c4;
        uint32_t a[2][4];
#pragma unroll
        for (int s = 0; s < 2; s++) {
            int qa = mt + s * 16 + r4;
            // k-slot pairing: channels (ks*8+2c4, ks*8+2c4+1) as slots (c4, c4+4)
            float2 A0 = *(const float2*)&a_sm[qa * 132 + ks * 8 + 2 * c4];
            float2 A1 = *(const float2*)&a_sm[(qa + 8) * 132 + ks * 8 + 2 * c4];
            a[s][0] = FU(A0.x); a[s][1] = FU(A1.x); a[s][2] = FU(A0.y); a[s][3] = FU(A1.y);
        }
        int kc0 = ks * 8 + 2 * c4;
#pragma unroll
        for (int nb = 0; nb < 4; nb++) {
            int ncol = nt + nb * 8 + r4;
            uint32_t b0 = FU(b_sm[kc0 * 264 + ncol]);
            uint32_t b1 = FU(b_sm[(kc0 + 1) * 264 + ncol]);
            mma_tf32(d[0][nb], a[0][0], a[0][1], a[0][2], a[0][3], b0, b1);
            mma_tf32(d[1][nb], a[1][0], a[1][1], a[1][2], a[1][3], b0, b1);
        }
        (void)kc;
    }
#pragma unroll
    for (int s = 0; s < 2; s++)
#pragma unroll
        for (int nb = 0; nb < 4; nb++) {
            int m0 = mt + s * 16 + r4;
            int n0 = nt + nb * 8 + 2 * c4;
            float2 lo = make_float2(d[s][nb][0], d[s][nb][1]);
            float2 hi = make_float2(d[s][nb][2], d[s][nb][3]);
            if (rnd) {
                lo.x = tf32r(lo.x); lo.y = tf32r(lo.y);
                hi.x = tf32r(hi.x); hi.y = tf32r(hi.y);
            }
            *(float2*)(Yb + (size_t)m0 * ld + n0)       = lo;
            *(float2*)(Yb + (size_t)(m0 + 8) * ld + n0) = hi;
        }
}

__global__ void __launch_bounds__(1024) gemm_tf32_kernel(
    const float* __restrict__ A, const float* __restrict__ X,
    float* __restrict__ Y, int ld, int ntiles)
{
    int b  = blockIdx.x / ntiles;
    int pb = (blockIdx.x % ntiles) * 256;
    gemm_tf32_tile(A, X + (size_t)b * 128 * ld + pb, Y + (size_t)b * 128 * ld + pb, ld, 0);
}

__global__ void __launch_bounds__(1024) gemm_kv_tf32_kernel(
    const float* __restrict__ wk, const float* __restrict__ wv)
{
    int sel = blockIdx.x >> 3;
    int b   = blockIdx.x & 7;
    const float* A = sel ? wv : wk;
    float* Y = sel ? g_v : g_k;
    // pre-round k/v to tf32 so attn's staging skips the cvt
    gemm_tf32_tile(A, g_xs + (size_t)b * 128 * NKV_, Y + (size_t)b * 128 * NKV_, NKV_, 1);
}

// ---------------- fused offset pipeline ----------------
__global__ void __launch_bounds__(1024) offset_kernel(
    const float* __restrict__ x, const float* __restrict__ w_dw,
    const float* __restrict__ ln_w, const float* __restrict__ w_off)
{
    __shared__ float off_sm[64 * 65];
    __shared__ float ws_sm[1600];
    __shared__ float pos_y[64], pos_x[64], dm_sm[64];

    int tid = threadIdx.x;
    int bg  = blockIdx.x >> 2;
    int qtr = blockIdx.x & 3;
    int b = bg >> 1, g = bg & 1;

    for (int i = tid; i < 1600; i += 1024) ws_sm[i] = w_dw[i];
    __syncthreads();

    for (int r = tid; r < 4096; r += 1024) {
        int c = r >> 6, spl = r & 63;
        int sp = qtr * 64 + spl;
        int i = sp >> 4, j = sp & 15;
        int y0 = 4 * i - 2, x0 = 4 * j - 2;
        const float* plane = g_q + ((size_t)(b * 128 + g * 64 + c)) * HW_;
        const float* ws = ws_sm + c * 25;
        float acc = 0.f;
#pragma unroll
        for (int u = 0; u < 5; u++) {
            int yy = y0 + u;
            if ((unsigned)yy < 64u) {
#pragma unroll
                for (int v = 0; v < 5; v++) {
                    int xx = x0 + v;
                    if ((unsigned)xx < 64u) acc += plane[yy * 64 + xx] * ws[u * 5 + v];
                }
            }
        }
        off_sm[c * 65 + spl] = acc;
    }
    __syncthreads();

    if (tid < 64) {
        int spl = tid;
        int sp = qtr * 64 + spl;
        float s = 0.f, s2 = 0.f;
#pragma unroll 8
        for (int c = 0; c < 64; c++) {
            float t = off_sm[c * 65 + spl];
            s += t; s2 += t * t;
        }
        float mean = s * (1.f / 64.f);
        float var  = s2 * (1.f / 64.f) - mean * mean;
        float rstd = rsqrtf(var + 1e-5f);
        float o0 = 0.f, o1 = 0.f, o2 = 0.f;
#pragma unroll 8
        for (int c = 0; c < 64; c++) {
            float t = off_sm[c * 65 + spl] * rstd * __ldg(&ln_w[c]);
            float ge = 0.5f * t * (1.f + erff(t * 0.70710678118654752f));
            o0 += __ldg(&w_off[c]) * ge;
            o1 += __ldg(&w_off[64 + c]) * ge;
            o2 += __ldg(&w_off[128 + c]) * ge;
        }
        int i = sp >> 4, j = sp & 15;
        float ry = (float)(2 * i + 1) * (1.f / 16.f) - 1.f;
        float rx = (float)(2 * j + 1) * (1.f / 16.f) - 1.f;
        float py = tanhf(o0) * (1.f / 16.f) + ry;
        float px = tanhf(o1) * (1.f / 16.f) + rx;
        pos_y[spl] = py;
        pos_x[spl] = px;
        dm_sm[spl] = 1.f / (1.f + expf(-o2));
        g_pos[bg * 512 + sp * 2]     = py;
        g_pos[bg * 512 + sp * 2 + 1] = px;
    }
    __syncthreads();

    for (int r = tid; r < 4096; r += 1024) {
        int c = r >> 6, spl = r & 63;
        int n = qtr * 64 + spl;
        const float* plane = x + ((size_t)(b * 128 + g * 64 + c)) * HW_;
        float gx = fminf((pos_x[spl] + 1.f) * 31.5f, 62.99999f);
        float gy = fminf((pos_y[spl] + 1.f) * 31.5f, 62.99999f);
        float x0f = floorf(gx), y0f = floorf(gy);
        float wx = gx - x0f, wy = gy - y0f;
        int ix0 = (int)x0f, iy0 = (int)y0f;
        const float* row0 = plane + iy0 * 64 + ix0;
        float v00 = row0[0], v01 = row0[1];
        float v10 = row0[64], v11 = row0[65];
        float top = v00 + (v01 - v00) * wx;
        float bot = v10 + (v11 - v10) * wx;
        float val = top + (bot - top) * wy;
        g_xs[((size_t)(b * 128 + g * 64 + c)) * NKV_ + n] = val * dm_sm[spl];
    }
}

// ---------------- fused attention v10: paired LDS.64 fragments ----------------
#define SMA_RPE  0                        // 16129 (+3 pad), pre-scaled by log2e
#define SMA_K    16132                    // [256][36] k transposed (tf32 pre-rounded)
#define SMA_VS   (SMA_K + 9216)           // [32 blk][32 c][8 n] stride 296 (tf32)
#define SMA_PT   (SMA_VS + 9472)          // [64][260] exp(scores); psum overlay [4][64][36]
#define SMA_GTB  (SMA_PT + 16640)         // [256] float4 {bx, wy0, wy1, packed rows}
#define SMA_RED  (SMA_GTB + 1024)         // [8][64] partial sums
#define SMA_QD   (SMA_RED + 512)          // [64][36] q*scale
#define ATTNA_FLOATS (SMA_QD + 2304)      // 55300 floats = 221200 B

#define LOG2E_ 1.4426950408889634f

// Unguarded x-only bilinear: rpe grid coords provably interior.
__device__ __forceinline__ float bilin2(const float* __restrict__ rpe_sm,
                                        float gx, float wy0, float wy1,
                                        int r0, int r1)
{
    float x0f = floorf(gx);
    float wx = gx - x0f;
    int ix0 = (int)x0f;
    float v00 = rpe_sm[r0 + ix0], v01 = rpe_sm[r0 + ix0 + 1];
    float v10 = rpe_sm[r1 + ix0], v11 = rpe_sm[r1 + ix0 + 1];
    float t0 = v00 + (v01 - v00) * wx;
    float t1 = v10 + (v11 - v10) * wx;
    return t0 * wy0 + t1 * wy1;
}

__global__ void __launch_bounds__(1024) attn_kernel(const float* __restrict__ rpe,
                                                    float* __restrict__ outp, int nt)
{
    extern __shared__ float sm[];
    float* rpe_sm = sm + SMA_RPE;
    float* k_sm   = sm + SMA_K;
    float* vs_sm  = sm + SMA_VS;
    float* pt_sm  = sm + SMA_PT;
    float4* gtb   = (float4*)(sm + SMA_GTB);
    float* red    = sm + SMA_RED;
    float* qd_sm  = sm + SMA_QD;

    int tid = threadIdx.x;
    int bh    = blockIdx.x >> 4;
    int group = blockIdx.x & 15;
    int b = bh >> 2, h = bh & 3, g = h >> 1;

    // ---- per-head loads ----
    const float* rp = rpe + (size_t)h * RPE_N;
    for (int i = tid; i < RPE_N; i += 1024) rpe_sm[i] = rp[i] * LOG2E_;

    const float* kb = g_k + ((size_t)(b * 128 + h * 32)) * NKV_;
    for (int i = tid; i < 8192; i += 1024) {
        int c = i >> 8, n = i & 255;
        k_sm[n * 36 + c] = kb[i];                 // already tf32-rounded
    }
    const float* vb = g_v + ((size_t)(b * 128 + h * 32)) * NKV_;
    for (int i = tid; i < 8192; i += 1024) {
        int c = i >> 8, n = i & 255;
        vs_sm[(n >> 3) * 296 + c * 8 + (n & 7)] = vb[i];   // [blk][c][8n]
    }

    float ppy = 0.f, ppx = 0.f;
    if (tid < 256) {
        float2 p2 = ((const float2*)(g_pos + (size_t)(b * 2 + g) * 512))[tid];
        ppy = p2.x; ppx = p2.y;
    }

    int lane = tid & 31, w = tid >> 5;
    int r4 = lane >> 2, c4 = lane & 3;
    // QK mapping
    int mblk = w & 3;       // q block of 16
    int ngrp = w >> 2;      // n group of 32
    // PV mapping: 8 tiles (4 qb x 2 cb) x 4 k-quarters
    int pvt = w & 7, kq = w >> 3;
    int qm  = (pvt & 3) * 16;
    int cv0 = (pvt >> 2) * 16;

    const float scale2 = 0.17677669529663687f * LOG2E_;

    for (int t = 0; t < nt; t++) {
        int tile = group * 4 + t;
        int qbase = tile * 64;
        __syncthreads();

        // per-tile bias tables (y-half hoisted)
        if (tid < 256) {
            float qy315 = (float)(2 * tile + 1) * 0.4921875f - 31.5f;
            float gy = qy315 + 63.f - 31.5f * ppy;
            float bx = 63.f - 31.5f * ppx;
            float y0f = floorf(gy);
            float wy = gy - y0f;
            unsigned r0 = (unsigned)((int)y0f * 127);
            gtb[tid] = make_float4(bx, 1.f - wy, wy, __uint_as_float(r0 | ((r0 + 127) << 16)));
        }
        // q load [q][36], scaled, tf32-rounded
        const float* qb = g_q + ((size_t)(b * 128 + h * 32)) * HW_ + qbase;
        for (int i = tid; i < 2048; i += 1024) {
            int c = i >> 6, qi = i & 63;
            qd_sm[qi * 36 + c] = tf32r(qb[(size_t)c * HW_ + qi] * scale2);
        }
        __syncthreads();

        // ---- QK via tf32 mma: warp = 16q x 32n, paired LDS.64 fragments ----
        float d[4][4];
#pragma unroll
        for (int i = 0; i < 4; i++)
#pragma unroll
            for (int j = 0; j < 4; j++) d[i][j] = 0.f;

        int qa = mblk * 16 + r4;
#pragma unroll
        for (int ks = 0; ks < 4; ks++) {
            int kc0 = ks * 8 + 2 * c4;   // channels (kc0, kc0+1) as slots (c4, c4+4)
            float2 A0 = *(const float2*)&qd_sm[qa * 36 + kc0];
            float2 A1 = *(const float2*)&qd_sm[(qa + 8) * 36 + kc0];
#pragma unroll
            for (int nb = 0; nb < 4; nb++) {
                int ncol = ngrp * 32 + nb * 8 + r4;
                float2 Bv = *(const float2*)&k_sm[ncol * 36 + kc0];
                mma_tf32(d[nb], FU(A0.x), FU(A1.x), FU(A0.y), FU(A1.y), FU(Bv.x), FU(Bv.y));
            }
        }

        // ---- fused bias + exp2 + store + partial sums ----
        {
            float axl = (float)(2 * (mblk * 16 + r4) + 1) * 0.4921875f - 31.5f;
            float axh = axl + 7.875f;
            float suml = 0.f, sumh = 0.f;
#pragma unroll
            for (int nb = 0; nb < 4; nb++) {
                int nn = ngrp * 32 + nb * 8 + 2 * c4;
                float4 G0 = gtb[nn], G1 = gtb[nn + 1];
                uint32_t u0 = __float_as_uint(G0.w);
                uint32_t u1 = __float_as_uint(G1.w);
                int r00 = u0 & 0xffff, r01 = u0 >> 16;
                int r10 = u1 & 0xffff, r11 = u1 >> 16;
                float e0 = ex2f(d[nb][0] + bilin2(rpe_sm, axl + G0.x, G0.y, G0.z, r00, r01));
                float e1 = ex2f(d[nb][1] + bilin2(rpe_sm, axl + G1.x, G1.y, G1.z, r10, r11));
                float e2 = ex2f(d[nb][2] + bilin2(rpe_sm, axh + G0.x, G0.y, G0.z, r00, r01));
                float e3 = ex2f(d[nb][3] + bilin2(rpe_sm, axh + G1.x, G1.y, G1.z, r10, r11));
                suml += e0 + e1;
                sumh += e2 + e3;
                int qrow = mblk * 16 + r4;
                *(float2*)&pt_sm[qrow * 260 + nn]       = make_float2(tf32r(e0), tf32r(e1));
                *(float2*)&pt_sm[(qrow + 8) * 260 + nn] = make_float2(tf32r(e2), tf32r(e3));
            }
            suml += __shfl_xor_sync(0xffffffffu, suml, 1);
            suml += __shfl_xor_sync(0xffffffffu, suml, 2);
            sumh += __shfl_xor_sync(0xffffffffu, sumh, 1);
            sumh += __shfl_xor_sync(0xffffffffu, sumh, 2);
            if (c4 == 0) {
                red[ngrp * 64 + mblk * 16 + r4]     = suml;
                red[ngrp * 64 + mblk * 16 + r4 + 8] = sumh;
            }
        }
        __syncthreads();

        // ---- PV via tf32 mma: warp = 16q x 16c x 64k, paired LDS.64 ----
        // k-slots (c4, c4+4) consume pt cols (kk+2c4, kk+2c4+1) and the
        // matching V keys from vs_sm's [blk][c][8n] layout.
        float dd0[4] = {0.f, 0.f, 0.f, 0.f};
        float dd1[4] = {0.f, 0.f, 0.f, 0.f};
#pragma unroll
        for (int ks = 0; ks < 8; ks++) {
            int kk = kq * 64 + ks * 8;
            int vsb = (kq * 8 + ks) * 296 + 2 * c4;
            float2 A0 = *(const float2*)&pt_sm[(qm + r4) * 260 + kk + 2 * c4];
            float2 A1 = *(const float2*)&pt_sm[(qm + 8 + r4) * 260 + kk + 2 * c4];
            float2 B0 = *(const float2*)&vs_sm[vsb + (cv0 + r4) * 8];
            float2 B1 = *(const float2*)&vs_sm[vsb + (cv0 + 8 + r4) * 8];
            mma_tf32(dd0, FU(A0.x), FU(A1.x), FU(A0.y), FU(A1.y), FU(B0.x), FU(B0.y));
            mma_tf32(dd1, FU(A0.x), FU(A1.x), FU(A0.y), FU(A1.y), FU(B1.x), FU(B1.y));
        }
        __syncthreads();   // all PV reads of pt done; overlay psum [4][64][36]
        {
            float* ps = pt_sm + kq * 2304;
            *(float2*)&ps[(qm + r4) * 36 + cv0 + 2 * c4]         = make_float2(dd0[0], dd0[1]);
            *(float2*)&ps[(qm + 8 + r4) * 36 + cv0 + 2 * c4]     = make_float2(dd0[2], dd0[3]);
            *(float2*)&ps[(qm + r4) * 36 + cv0 + 8 + 2 * c4]     = make_float2(dd1[0], dd1[1]);
            *(float2*)&ps[(qm + 8 + r4) * 36 + cv0 + 8 + 2 * c4] = make_float2(dd1[2], dd1[3]);
        }
        __syncthreads();

        // ---- epilogue ----
        {
            int qq = tid & 63;
            int ci = tid >> 6;
            float tot = 0.f;
#pragma unroll
            for (int k = 0; k < 8; k++) tot += red[k * 64 + qq];
            float inv = 1.f / tot;
            float* ob = outp + ((size_t)(b * 128 + h * 32)) * HW_ + qbase + qq;
#pragma unroll
            for (int u = 0; u < 2; u++) {
                int cc = ci + u * 16;
                float sv = pt_sm[qq * 36 + cc]
                         + pt_sm[2304 + qq * 36 + cc]
                         + pt_sm[4608 + qq * 36 + cc]
                         + pt_sm[6912 + qq * 36 + cc];
                ob[(size_t)cc * HW_] = sv * inv;
            }
        }
    }
}

// ---------------- launch ----------------
extern "C" void kernel_launch(void* const* d_in, const int* in_sizes, int n_in,
                              void* d_out, int out_size)
{
    const float* x     = (const float*)d_in[0];
    const float* w_dw  = (const float*)d_in[1];
    const float* ln_w  = (const float*)d_in[2];
    const float* w_off = (const float*)d_in[3];
    const float* wq    = (const float*)d_in[4];
    const float* wk    = (const float*)d_in[5];
    const float* wv    = (const float*)d_in[6];
    const float* wo    = (const float*)d_in[7];
    const float* rpe   = (const float*)d_in[8];
    float* out = (float*)d_out;

    float *gq, *gao;
    cudaGetSymbolAddress((void**)&gq, g_q);
    cudaGetSymbolAddress((void**)&gao, g_ao);

    cudaFuncSetAttribute(gemm_tf32_kernel, cudaFuncAttributeMaxDynamicSharedMemorySize, GT_FLOATS * 4);
    cudaFuncSetAttribute(gemm_kv_tf32_kernel, cudaFuncAttributeMaxDynamicSharedMemorySize, GT_FLOATS * 4);
    cudaFuncSetAttribute(attn_kernel, cudaFuncAttributeMaxDynamicSharedMemorySize,
                         ATTNA_FLOATS * 4);

    // 1: q projection (tf32 mma)
    gemm_tf32_kernel<<<128, 1024, GT_FLOATS * 4>>>(wq, x, gq, HW_, 16);
    // 2: fused offset pipeline
    offset_kernel<<<64, 1024>>>(x, w_dw, ln_w, w_off);
    // 3: k/v projections (tf32 mma, outputs pre-rounded to tf32)
    gemm_kv_tf32_kernel<<<16, 1024, GT_FLOATS * 4>>>(wk, wv);
    // 4: fused attention (ncu capture slot)
    attn_kernel<<<512, 1024, ATTNA_FLOATS * 4>>>(rpe, gao, 4);
    // 5: output projection (tf32 mma)
    gemm_tf32_kernel<<<128, 1024, GT_FLOATS * 4>>>(wo, gao, out, HW_, 16);
}

// round 13
// speedup vs baseline: 1.2513x; 1.2513x over previous
#include <cuda_runtime.h>
#include <math.h>
#include <stdint.h>

// ---------------- problem constants ----------------
#define B_   8
#define C_   128
#define HW_  4096
#define NKV_ 256
#define RPE_N 16129     // 127*127

// ---------------- helpers ----------------
__device__ __forceinline__ float ex2f(float x) {
    float r;
    asm("ex2.approx.f32 %0, %1;" : "=f"(r) : "f"(x));
    return r;
}
__device__ __forceinline__ float tf32r(float x) {
    uint32_t u;
    asm("cvt.rna.tf32.f32 %0, %1;" : "=r"(u) : "f"(x));
    return __uint_as_float(u);
}
__device__ __forceinline__ uint32_t h2pack(float lo, float hi) {
    uint32_t r;
    asm("cvt.rn.f16x2.f32 %0, %1, %2;" : "=r"(r) : "f"(hi), "f"(lo));
    return r;
}
__device__ __forceinline__ void mma_tf32(float d[4],
    uint32_t a0, uint32_t a1, uint32_t a2, uint32_t a3,
    uint32_t b0, uint32_t b1)
{
    asm volatile(
        "mma.sync.aligned.m16n8k8.row.col.f32.tf32.tf32.f32 "
        "{%0,%1,%2,%3}, {%4,%5,%6,%7}, {%8,%9}, {%0,%1,%2,%3};"
        : "+f"(d[0]), "+f"(d[1]), "+f"(d[2]), "+f"(d[3])
        : "r"(a0), "r"(a1), "r"(a2), "r"(a3), "r"(b0), "r"(b1));
}
__device__ __forceinline__ void mma_f16(float d[4],
    uint32_t a0, uint32_t a1, uint32_t a2, uint32_t a3,
    uint32_t b0, uint32_t b1)
{
    asm volatile(
        "mma.sync.aligned.m16n8k16.row.col.f32.f16.f16.f32 "
        "{%0,%1,%2,%3}, {%4,%5,%6,%7}, {%8,%9}, {%0,%1,%2,%3};"
        : "+f"(d[0]), "+f"(d[1]), "+f"(d[2]), "+f"(d[3])
        : "r"(a0), "r"(a1), "r"(a2), "r"(a3), "r"(b0), "r"(b1));
}
#define FU(x) __float_as_uint(x)

// ---------------- device scratch ----------------
__device__ float g_q  [B_ * C_ * HW_];
__device__ float g_ao [B_ * C_ * HW_];
__device__ float g_pos[16 * NKV_ * 2];
__device__ float g_xs [B_ * C_ * NKV_];
__device__ float g_k  [B_ * C_ * NKV_];
__device__ float g_v  [B_ * C_ * NKV_];

// ---------------- tf32 mma GEMM (R11 form — conflict-free addressing) ----------------
#define GT_FLOATS (16896 + 33792)   // 50688 floats = 202752 B

__device__ __forceinline__ void gemm_tf32_tile(
    const float* __restrict__ A, const float* __restrict__ Xb,
    float* __restrict__ Yb, int ld, int rnd)
{
    extern __shared__ float sm[];
    float* a_sm = sm;
    float* b_sm = sm + 16896;
    int tid = threadIdx.x;

    for (int i = tid; i < 4096; i += 1024) {
        int m = i >> 5, k0 = (i & 31) * 4;
        float4 v = *(const float4*)(A + m * 128 + k0);
        float* d = a_sm + m * 132 + k0;
        d[0] = tf32r(v.x); d[1] = tf32r(v.y); d[2] = tf32r(v.z); d[3] = tf32r(v.w);
    }
    for (int i = tid; i < 8192; i += 1024) {
        int k = i >> 6, n0 = (i & 63) * 4;
        float4 v = *(const float4*)(Xb + (size_t)k * ld + n0);
        float* d = b_sm + k * 264 + n0;
        d[0] = tf32r(v.x); d[1] = tf32r(v.y); d[2] = tf32r(v.z); d[3] = tf32r(v.w);
    }
    __syncthreads();

    int lane = tid & 31, w = tid >> 5;
    int r4 = lane >> 2, c4 = lane & 3;
    int mt = (w >> 3) * 32;
    int nt = (w & 7) * 32;

    float d[2][4][4];
#pragma unroll
    for (int s = 0; s < 2; s++)
#pragma unroll
        for (int nb = 0; nb < 4; nb++)
#pragma unroll
            for (int j = 0; j < 4; j++) d[s][nb][j] = 0.f;

#pragma unroll
    for (int ks = 0; ks < 16; ks++) {
        int kc = ks * 8 + c4;
        uint32_t a[2][4];
#pragma unroll
        for (int s = 0; s < 2; s++) {
            int qa = mt + s * 16 + r4;
            a[s][0] = FU(a_sm[qa * 132 + kc]);
            a[s][1] = FU(a_sm[(qa + 8) * 132 + kc]);
            a[s][2] = FU(a_sm[qa * 132 + kc + 4]);
            a[s][3] = FU(a_sm[(qa + 8) * 132 + kc + 4]);
        }
#pragma unroll
        for (int nb = 0; nb < 4; nb++) {
            int ncol = nt + nb * 8 + r4;
            uint32_t b0 = FU(b_sm[kc * 264 + ncol]);
            uint32_t b1 = FU(b_sm[(kc + 4) * 264 + ncol]);
            mma_tf32(d[0][nb], a[0][0], a[0][1], a[0][2], a[0][3], b0, b1);
            mma_tf32(d[1][nb], a[1][0], a[1][1], a[1][2], a[1][3], b0, b1);
        }
    }
#pragma unroll
    for (int s = 0; s < 2; s++)
#pragma unroll
        for (int nb = 0; nb < 4; nb++) {
            int m0 = mt + s * 16 + r4;
            int n0 = nt + nb * 8 + 2 * c4;
            float2 lo = make_float2(d[s][nb][0], d[s][nb][1]);
            float2 hi = make_float2(d[s][nb][2], d[s][nb][3]);
            if (rnd) {
                lo.x = tf32r(lo.x); lo.y = tf32r(lo.y);
                hi.x = tf32r(hi.x); hi.y = tf32r(hi.y);
            }
            *(float2*)(Yb + (size_t)m0 * ld + n0)       = lo;
            *(float2*)(Yb + (size_t)(m0 + 8) * ld + n0) = hi;
        }
}

__global__ void __launch_bounds__(1024) gemm_tf32_kernel(
    const float* __restrict__ A, const float* __restrict__ X,
    float* __restrict__ Y, int ld, int ntiles)
{
    int b  = blockIdx.x / ntiles;
    int pb = (blockIdx.x % ntiles) * 256;
    gemm_tf32_tile(A, X + (size_t)b * 128 * ld + pb, Y + (size_t)b * 128 * ld + pb, ld, 0);
}

__global__ void __launch_bounds__(1024) gemm_kv_tf32_kernel(
    const float* __restrict__ wk, const float* __restrict__ wv)
{
    int sel = blockIdx.x >> 3;
    int b   = blockIdx.x & 7;
    const float* A = sel ? wv : wk;
    float* Y = sel ? g_v : g_k;
    gemm_tf32_tile(A, g_xs + (size_t)b * 128 * NKV_, Y + (size_t)b * 128 * NKV_, NKV_, 1);
}

// ---------------- fused offset pipeline ----------------
__global__ void __launch_bounds__(1024) offset_kernel(
    const float* __restrict__ x, const float* __restrict__ w_dw,
    const float* __restrict__ ln_w, const float* __restrict__ w_off)
{
    __shared__ float off_sm[64 * 65];
    __shared__ float ws_sm[1600];
    __shared__ float pos_y[64], pos_x[64], dm_sm[64];

    int tid = threadIdx.x;
    int bg  = blockIdx.x >> 2;
    int qtr = blockIdx.x & 3;
    int b = bg >> 1, g = bg & 1;

    for (int i = tid; i < 1600; i += 1024) ws_sm[i] = w_dw[i];
    __syncthreads();

    for (int r = tid; r < 4096; r += 1024) {
        int c = r >> 6, spl = r & 63;
        int sp = qtr * 64 + spl;
        int i = sp >> 4, j = sp & 15;
        int y0 = 4 * i - 2, x0 = 4 * j - 2;
        const float* plane = g_q + ((size_t)(b * 128 + g * 64 + c)) * HW_;
        const float* ws = ws_sm + c * 25;
        float acc = 0.f;
#pragma unroll
        for (int u = 0; u < 5; u++) {
            int yy = y0 + u;
            if ((unsigned)yy < 64u) {
#pragma unroll
                for (int v = 0; v < 5; v++) {
                    int xx = x0 + v;
                    if ((unsigned)xx < 64u) acc += plane[yy * 64 + xx] * ws[u * 5 + v];
                }
            }
        }
        off_sm[c * 65 + spl] = acc;
    }
    __syncthreads();

    if (tid < 64) {
        int spl = tid;
        int sp = qtr * 64 + spl;
        float s = 0.f, s2 = 0.f;
#pragma unroll 8
        for (int c = 0; c < 64; c++) {
            float t = off_sm[c * 65 + spl];
            s += t; s2 += t * t;
        }
        float mean = s * (1.f / 64.f);
        float var  = s2 * (1.f / 64.f) - mean * mean;
        float rstd = rsqrtf(var + 1e-5f);
        float o0 = 0.f, o1 = 0.f, o2 = 0.f;
#pragma unroll 8
        for (int c = 0; c < 64; c++) {
            float t = off_sm[c * 65 + spl] * rstd * __ldg(&ln_w[c]);
            float ge = 0.5f * t * (1.f + erff(t * 0.70710678118654752f));
            o0 += __ldg(&w_off[c]) * ge;
            o1 += __ldg(&w_off[64 + c]) * ge;
            o2 += __ldg(&w_off[128 + c]) * ge;
        }
        int i = sp >> 4, j = sp & 15;
        float ry = (float)(2 * i + 1) * (1.f / 16.f) - 1.f;
        float rx = (float)(2 * j + 1) * (1.f / 16.f) - 1.f;
        float py = tanhf(o0) * (1.f / 16.f) + ry;
        float px = tanhf(o1) * (1.f / 16.f) + rx;
        pos_y[spl] = py;
        pos_x[spl] = px;
        dm_sm[spl] = 1.f / (1.f + expf(-o2));
        g_pos[bg * 512 + sp * 2]     = py;
        g_pos[bg * 512 + sp * 2 + 1] = px;
    }
    __syncthreads();

    for (int r = tid; r < 4096; r += 1024) {
        int c = r >> 6, spl = r & 63;
        int n = qtr * 64 + spl;
        const float* plane = x + ((size_t)(b * 128 + g * 64 + c)) * HW_;
        float gx = fminf((pos_x[spl] + 1.f) * 31.5f, 62.99999f);
        float gy = fminf((pos_y[spl] + 1.f) * 31.5f, 62.99999f);
        float x0f = floorf(gx), y0f = floorf(gy);
        float wx = gx - x0f, wy = gy - y0f;
        int ix0 = (int)x0f, iy0 = (int)y0f;
        const float* row0 = plane + iy0 * 64 + ix0;
        float v00 = row0[0], v01 = row0[1];
        float v10 = row0[64], v11 = row0[65];
        float top = v00 + (v01 - v00) * wx;
        float bot = v10 + (v11 - v10) * wx;
        float val = top + (bot - top) * wy;
        g_xs[((size_t)(b * 128 + g * 64 + c)) * NKV_ + n] = val * dm_sm[spl];
    }
}

// ---------------- fused attention v11: tf32 QK + fp16 PV ----------------
// smem layout (float indices)
#define SMB_RPE  0                        // 16129 (+3 pad), pre-scaled by log2e
#define SMB_K    16132                    // [256][36] k (tf32 pre-rounded)
#define SMB_VH   (SMB_K + 9216)           // [32 c][132] half2 of V key-pairs
#define SMB_PTH  (SMB_VH + 4224)          // [64 q][132] half2 of exp(scores) key-pairs
#define SMB_GTB  (SMB_PTH + 8448)         // [256] float4 {bx, wy0, wy1, packed rows}
#define SMB_RED  (SMB_GTB + 1024)         // [8][64] partial sums
#define SMB_QD   (SMB_RED + 512)          // [64][36] q*scale
#define SMB_PS   (SMB_QD + 2304)          // psum [4][64][36]
#define ATTNB_FLOATS (SMB_PS + 9216)      // 51076 floats = 204304 B

#define LOG2E_ 1.4426950408889634f

__device__ __forceinline__ float bilin2(const float* __restrict__ rpe_sm,
                                        float gx, float wy0, float wy1,
                                        int r0, int r1)
{
    float x0f = floorf(gx);
    float wx = gx - x0f;
    int ix0 = (int)x0f;
    float v00 = rpe_sm[r0 + ix0], v01 = rpe_sm[r0 + ix0 + 1];
    float v10 = rpe_sm[r1 + ix0], v11 = rpe_sm[r1 + ix0 + 1];
    float t0 = v00 + (v01 - v00) * wx;
    float t1 = v10 + (v11 - v10) * wx;
    return t0 * wy0 + t1 * wy1;
}

__global__ void __launch_bounds__(1024) attn_kernel(const float* __restrict__ rpe,
                                                    float* __restrict__ outp, int nt)
{
    extern __shared__ float sm[];
    float* rpe_sm = sm + SMB_RPE;
    float* k_sm   = sm + SMB_K;
    uint32_t* vh  = (uint32_t*)(sm + SMB_VH);
    uint32_t* pth = (uint32_t*)(sm + SMB_PTH);
    float4* gtb   = (float4*)(sm + SMB_GTB);
    float* red    = sm + SMB_RED;
    float* qd_sm  = sm + SMB_QD;
    float* psum   = sm + SMB_PS;

    int tid = threadIdx.x;
    int bh    = blockIdx.x >> 4;
    int group = blockIdx.x & 15;
    int b = bh >> 2, h = bh & 3, g = h >> 1;

    // ---- per-head loads ----
    const float* rp = rpe + (size_t)h * RPE_N;
    for (int i = tid; i < RPE_N; i += 1024) rpe_sm[i] = rp[i] * LOG2E_;

    const float* kb = g_k + ((size_t)(b * 128 + h * 32)) * NKV_;
    for (int i = tid; i < 8192; i += 1024) {
        int c = i >> 8, n = i & 255;
        k_sm[n * 36 + c] = kb[i];                 // already tf32-rounded
    }
    // V as half2 key-pairs: vh[c][np] = {V[c][2np], V[c][2np+1]}
    const float* vb = g_v + ((size_t)(b * 128 + h * 32)) * NKV_;
    for (int i = tid; i < 4096; i += 1024) {
        int c = i >> 7, np = i & 127;
        float2 v2 = *(const float2*)&vb[c * 256 + 2 * np];
        vh[c * 132 + np] = h2pack(v2.x, v2.y);
    }

    float ppy = 0.f, ppx = 0.f;
    if (tid < 256) {
        float2 p2 = ((const float2*)(g_pos + (size_t)(b * 2 + g) * 512))[tid];
        ppy = p2.x; ppx = p2.y;
    }

    int lane = tid & 31, w = tid >> 5;
    int r4 = lane >> 2, c4 = lane & 3;
    // QK mapping
    int mblk = w & 3;       // q block of 16
    int ngrp = w >> 2;      // n group of 32
    // PV mapping: 8 tiles (4 qb x 2 cb) x 4 k-quarters
    int pvt = w & 7, kq = w >> 3;
    int qm  = (pvt & 3) * 16;
    int cv0 = (pvt >> 2) * 16;

    const float scale2 = 0.17677669529663687f * LOG2E_;

    for (int t = 0; t < nt; t++) {
        int tile = group * 4 + t;
        int qbase = tile * 64;
        __syncthreads();   // protect pth/qd/gtb reuse across tiles

        // per-tile bias tables (y-half hoisted)
        if (tid < 256) {
            float qy315 = (float)(2 * tile + 1) * 0.4921875f - 31.5f;
            float gy = qy315 + 63.f - 31.5f * ppy;
            float bx = 63.f - 31.5f * ppx;
            float y0f = floorf(gy);
            float wy = gy - y0f;
            unsigned r0 = (unsigned)((int)y0f * 127);
            gtb[tid] = make_float4(bx, 1.f - wy, wy, __uint_as_float(r0 | ((r0 + 127) << 16)));
        }
        // q load [q][36], scaled, tf32-rounded
        const float* qb = g_q + ((size_t)(b * 128 + h * 32)) * HW_ + qbase;
        for (int i = tid; i < 2048; i += 1024) {
            int c = i >> 6, qi = i & 63;
            qd_sm[qi * 36 + c] = tf32r(qb[(size_t)c * HW_ + qi] * scale2);
        }
        __syncthreads();

        // ---- QK via tf32 mma: warp = 16q x 32n ----
        float d[4][4];
#pragma unroll
        for (int i = 0; i < 4; i++)
#pragma unroll
            for (int j = 0; j < 4; j++) d[i][j] = 0.f;

        int qa = mblk * 16 + r4;
#pragma unroll
        for (int ks = 0; ks < 4; ks++) {
            int kc = ks * 8 + c4;
            uint32_t a0 = FU(qd_sm[qa * 36 + kc]);
            uint32_t a1 = FU(qd_sm[(qa + 8) * 36 + kc]);
            uint32_t a2 = FU(qd_sm[qa * 36 + kc + 4]);
            uint32_t a3 = FU(qd_sm[(qa + 8) * 36 + kc + 4]);
#pragma unroll
            for (int nb = 0; nb < 4; nb++) {
                int ncol = ngrp * 32 + nb * 8 + r4;
                uint32_t b0 = FU(k_sm[ncol * 36 + kc]);
                uint32_t b1 = FU(k_sm[ncol * 36 + kc + 4]);
                mma_tf32(d[nb], a0, a1, a2, a3, b0, b1);
            }
        }

        // ---- fused bias + exp2 + half2 store + partial sums ----
        {
            float axl = (float)(2 * (mblk * 16 + r4) + 1) * 0.4921875f - 31.5f;
            float axh = axl + 7.875f;
            float suml = 0.f, sumh = 0.f;
            int qrow = mblk * 16 + r4;
#pragma unroll
            for (int nb = 0; nb < 4; nb++) {
                int nn = ngrp * 32 + nb * 8 + 2 * c4;     // even key index
                float4 G0 = gtb[nn], G1 = gtb[nn + 1];
                uint32_t u0 = __float_as_uint(G0.w);
                uint32_t u1 = __float_as_uint(G1.w);
                int r00 = u0 & 0xffff, r01 = u0 >> 16;
                int r10 = u1 & 0xffff, r11 = u1 >> 16;
                float e0 = ex2f(d[nb][0] + bilin2(rpe_sm, axl + G0.x, G0.y, G0.z, r00, r01));
                float e1 = ex2f(d[nb][1] + bilin2(rpe_sm, axl + G1.x, G1.y, G1.z, r10, r11));
                float e2 = ex2f(d[nb][2] + bilin2(rpe_sm, axh + G0.x, G0.y, G0.z, r00, r01));
                float e3 = ex2f(d[nb][3] + bilin2(rpe_sm, axh + G1.x, G1.y, G1.z, r10, r11));
                suml += e0 + e1;
                sumh += e2 + e3;
                int npi = (nn >> 1);                      // ngrp*16 + nb*4 + c4
                pth[qrow * 132 + npi]       = h2pack(e0, e1);
                pth[(qrow + 8) * 132 + npi] = h2pack(e2, e3);
            }
            suml += __shfl_xor_sync(0xffffffffu, suml, 1);
            suml += __shfl_xor_sync(0xffffffffu, suml, 2);
            sumh += __shfl_xor_sync(0xffffffffu, sumh, 1);
            sumh += __shfl_xor_sync(0xffffffffu, sumh, 2);
            if (c4 == 0) {
                red[ngrp * 64 + qrow]     = suml;
                red[ngrp * 64 + qrow + 8] = sumh;
            }
        }
        __syncthreads();

        // ---- PV via f16 mma (m16n8k16): warp = 16q x 16c x 64k ----
        float dd0[4] = {0.f, 0.f, 0.f, 0.f};
        float dd1[4] = {0.f, 0.f, 0.f, 0.f};
#pragma unroll
        for (int ks = 0; ks < 4; ks++) {
            int koff = kq * 32 + ks * 8;                  // half2 index of key base
            uint32_t a0 = pth[(qm + r4) * 132 + koff + c4];
            uint32_t a1 = pth[(qm + 8 + r4) * 132 + koff + c4];
            uint32_t a2 = pth[(qm + r4) * 132 + koff + c4 + 4];
            uint32_t a3 = pth[(qm + 8 + r4) * 132 + koff + c4 + 4];
            uint32_t b0 = vh[(cv0 + r4) * 132 + koff + c4];
            uint32_t b1 = vh[(cv0 + r4) * 132 + koff + c4 + 4];
            uint32_t b2 = vh[(cv0 + 8 + r4) * 132 + koff + c4];
            uint32_t b3 = vh[(cv0 + 8 + r4) * 132 + koff + c4 + 4];
            mma_f16(dd0, a0, a1, a2, a3, b0, b1);
            mma_f16(dd1, a0, a1, a2, a3, b2, b3);
        }
        // psum has its own region: no sync needed before store
        {
            float* ps = psum + kq * 2304;
            *(float2*)&ps[(qm + r4) * 36 + cv0 + 2 * c4]         = make_float2(dd0[0], dd0[1]);
            *(float2*)&ps[(qm + 8 + r4) * 36 + cv0 + 2 * c4]     = make_float2(dd0[2], dd0[3]);
            *(float2*)&ps[(qm + r4) * 36 + cv0 + 8 + 2 * c4]     = make_float2(dd1[0], dd1[1]);
            *(float2*)&ps[(qm + 8 + r4) * 36 + cv0 + 8 + 2 * c4] = make_float2(dd1[2], dd1[3]);
        }
        __syncthreads();

        // ---- epilogue ----
        {
            int qq = tid & 63;
            int ci = tid >> 6;
            float tot = 0.f;
#pragma unroll
            for (int k = 0; k < 8; k++) tot += red[k * 64 + qq];
            float inv = 1.f / tot;
            float* ob = outp + ((size_t)(b * 128 + h * 32)) * HW_ + qbase + qq;
#pragma unroll
            for (int u = 0; u < 2; u++) {
                int cc = ci + u * 16;
                float sv = psum[qq * 36 + cc]
                         + psum[2304 + qq * 36 + cc]
                         + psum[4608 + qq * 36 + cc]
                         + psum[6912 + qq * 36 + cc];
                ob[(size_t)cc * HW_] = sv * inv;
            }
        }
    }
}

// ---------------- launch ----------------
extern "C" void kernel_launch(void* const* d_in, const int* in_sizes, int n_in,
                              void* d_out, int out_size)
{
    const float* x     = (const float*)d_in[0];
    const float* w_dw  = (const float*)d_in[1];
    const float* ln_w  = (const float*)d_in[2];
    const float* w_off = (const float*)d_in[3];
    const float* wq    = (const float*)d_in[4];
    const float* wk    = (const float*)d_in[5];
    const float* wv    = (const float*)d_in[6];
    const float* wo    = (const float*)d_in[7];
    const float* rpe   = (const float*)d_in[8];
    float* out = (float*)d_out;

    float *gq, *gao;
    cudaGetSymbolAddress((void**)&gq, g_q);
    cudaGetSymbolAddress((void**)&gao, g_ao);

    cudaFuncSetAttribute(gemm_tf32_kernel, cudaFuncAttributeMaxDynamicSharedMemorySize, GT_FLOATS * 4);
    cudaFuncSetAttribute(gemm_kv_tf32_kernel, cudaFuncAttributeMaxDynamicSharedMemorySize, GT_FLOATS * 4);
    cudaFuncSetAttribute(attn_kernel, cudaFuncAttributeMaxDynamicSharedMemorySize,
                         ATTNB_FLOATS * 4);

    // 1: q projection (tf32 mma)
    gemm_tf32_kernel<<<128, 1024, GT_FLOATS * 4>>>(wq, x, gq, HW_, 16);
    // 2: fused offset pipeline
    offset_kernel<<<64, 1024>>>(x, w_dw, ln_w, w_off);
    // 3: k/v projections (tf32 mma, outputs pre-rounded)
    gemm_kv_tf32_kernel<<<16, 1024, GT_FLOATS * 4>>>(wk, wv);
    // 4: fused attention (ncu capture slot)
    attn_kernel<<<512, 1024, ATTNB_FLOATS * 4>>>(rpe, gao, 4);
    // 5: output projection (tf32 mma)
    gemm_tf32_kernel<<<128, 1024, GT_FLOATS * 4>>>(wo, gao, out, HW_, 16);
}

// round 14
// speedup vs baseline: 1.3614x; 1.0880x over previous
#include <cuda_runtime.h>
#include <math.h>
#include <stdint.h>

// ---------------- problem constants ----------------
#define B_   8
#define C_   128
#define HW_  4096
#define NKV_ 256
#define RPE_N 16129     // 127*127

// ---------------- helpers ----------------
__device__ __forceinline__ float ex2f(float x) {
    float r;
    asm("ex2.approx.f32 %0, %1;" : "=f"(r) : "f"(x));
    return r;
}
__device__ __forceinline__ float tf32r(float x) {
    uint32_t u;
    asm("cvt.rna.tf32.f32 %0, %1;" : "=r"(u) : "f"(x));
    return __uint_as_float(u);
}
__device__ __forceinline__ uint32_t h2pack(float lo, float hi) {
    uint32_t r;
    asm("cvt.rn.f16x2.f32 %0, %1, %2;" : "=r"(r) : "f"(hi), "f"(lo));
    return r;
}
__device__ __forceinline__ void mma_tf32(float d[4],
    uint32_t a0, uint32_t a1, uint32_t a2, uint32_t a3,
    uint32_t b0, uint32_t b1)
{
    asm volatile(
        "mma.sync.aligned.m16n8k8.row.col.f32.tf32.tf32.f32 "
        "{%0,%1,%2,%3}, {%4,%5,%6,%7}, {%8,%9}, {%0,%1,%2,%3};"
        : "+f"(d[0]), "+f"(d[1]), "+f"(d[2]), "+f"(d[3])
        : "r"(a0), "r"(a1), "r"(a2), "r"(a3), "r"(b0), "r"(b1));
}
__device__ __forceinline__ void mma_f16(float d[4],
    uint32_t a0, uint32_t a1, uint32_t a2, uint32_t a3,
    uint32_t b0, uint32_t b1)
{
    asm volatile(
        "mma.sync.aligned.m16n8k16.row.col.f32.f16.f16.f32 "
        "{%0,%1,%2,%3}, {%4,%5,%6,%7}, {%8,%9}, {%0,%1,%2,%3};"
        : "+f"(d[0]), "+f"(d[1]), "+f"(d[2]), "+f"(d[3])
        : "r"(a0), "r"(a1), "r"(a2), "r"(a3), "r"(b0), "r"(b1));
}
#define FU(x) __float_as_uint(x)

// ---------------- device scratch ----------------
__device__ float g_q  [B_ * C_ * HW_];
__device__ float g_ao [B_ * C_ * HW_];
__device__ float g_pos[16 * NKV_ * 2];
__device__ float g_xs [B_ * C_ * NKV_];
__device__ float g_k  [B_ * C_ * NKV_];
__device__ float g_v  [B_ * C_ * NKV_];

// ---------------- tf32 mma GEMM (R11 form — conflict-free addressing) ----------------
#define GT_FLOATS (16896 + 33792)   // 50688 floats = 202752 B

__device__ __forceinline__ void gemm_tf32_tile(
    const float* __restrict__ A, const float* __restrict__ Xb,
    float* __restrict__ Yb, int ld, int rnd)
{
    extern __shared__ float sm[];
    float* a_sm = sm;
    float* b_sm = sm + 16896;
    int tid = threadIdx.x;

    for (int i = tid; i < 4096; i += 1024) {
        int m = i >> 5, k0 = (i & 31) * 4;
        float4 v = *(const float4*)(A + m * 128 + k0);
        float* d = a_sm + m * 132 + k0;
        d[0] = tf32r(v.x); d[1] = tf32r(v.y); d[2] = tf32r(v.z); d[3] = tf32r(v.w);
    }
    for (int i = tid; i < 8192; i += 1024) {
        int k = i >> 6, n0 = (i & 63) * 4;
        float4 v = *(const float4*)(Xb + (size_t)k * ld + n0);
        float* d = b_sm + k * 264 + n0;
        d[0] = tf32r(v.x); d[1] = tf32r(v.y); d[2] = tf32r(v.z); d[3] = tf32r(v.w);
    }
    __syncthreads();

    int lane = tid & 31, w = tid >> 5;
    int r4 = lane >> 2, c4 = lane & 3;
    int mt = (w >> 3) * 32;
    int nt = (w & 7) * 32;

    float d[2][4][4];
#pragma unroll
    for (int s = 0; s < 2; s++)
#pragma unroll
        for (int nb = 0; nb < 4; nb++)
#pragma unroll
            for (int j = 0; j < 4; j++) d[s][nb][j] = 0.f;

#pragma unroll
    for (int ks = 0; ks < 16; ks++) {
        int kc = ks * 8 + c4;
        uint32_t a[2][4];
#pragma unroll
        for (int s = 0; s < 2; s++) {
            int qa = mt + s * 16 + r4;
            a[s][0] = FU(a_sm[qa * 132 + kc]);
            a[s][1] = FU(a_sm[(qa + 8) * 132 + kc]);
            a[s][2] = FU(a_sm[qa * 132 + kc + 4]);
            a[s][3] = FU(a_sm[(qa + 8) * 132 + kc + 4]);
        }
#pragma unroll
        for (int nb = 0; nb < 4; nb++) {
            int ncol = nt + nb * 8 + r4;
            uint32_t b0 = FU(b_sm[kc * 264 + ncol]);
            uint32_t b1 = FU(b_sm[(kc + 4) * 264 + ncol]);
            mma_tf32(d[0][nb], a[0][0], a[0][1], a[0][2], a[0][3], b0, b1);
            mma_tf32(d[1][nb], a[1][0], a[1][1], a[1][2], a[1][3], b0, b1);
        }
    }
#pragma unroll
    for (int s = 0; s < 2; s++)
#pragma unroll
        for (int nb = 0; nb < 4; nb++) {
            int m0 = mt + s * 16 + r4;
            int n0 = nt + nb * 8 + 2 * c4;
            float2 lo = make_float2(d[s][nb][0], d[s][nb][1]);
            float2 hi = make_float2(d[s][nb][2], d[s][nb][3]);
            if (rnd) {
                lo.x = tf32r(lo.x); lo.y = tf32r(lo.y);
                hi.x = tf32r(hi.x); hi.y = tf32r(hi.y);
            }
            *(float2*)(Yb + (size_t)m0 * ld + n0)       = lo;
            *(float2*)(Yb + (size_t)(m0 + 8) * ld + n0) = hi;
        }
}

__global__ void __launch_bounds__(1024) gemm_tf32_kernel(
    const float* __restrict__ A, const float* __restrict__ X,
    float* __restrict__ Y, int ld, int ntiles)
{
    int b  = blockIdx.x / ntiles;
    int pb = (blockIdx.x % ntiles) * 256;
    gemm_tf32_tile(A, X + (size_t)b * 128 * ld + pb, Y + (size_t)b * 128 * ld + pb, ld, 0);
}

__global__ void __launch_bounds__(1024) gemm_kv_tf32_kernel(
    const float* __restrict__ wk, const float* __restrict__ wv)
{
    int sel = blockIdx.x >> 3;
    int b   = blockIdx.x & 7;
    const float* A = sel ? wv : wk;
    float* Y = sel ? g_v : g_k;
    gemm_tf32_tile(A, g_xs + (size_t)b * 128 * NKV_, Y + (size_t)b * 128 * NKV_, NKV_, 1);
}

// ---------------- fused offset pipeline ----------------
__global__ void __launch_bounds__(1024) offset_kernel(
    const float* __restrict__ x, const float* __restrict__ w_dw,
    const float* __restrict__ ln_w, const float* __restrict__ w_off)
{
    __shared__ float off_sm[64 * 65];
    __shared__ float ws_sm[1600];
    __shared__ float pos_y[64], pos_x[64], dm_sm[64];

    int tid = threadIdx.x;
    int bg  = blockIdx.x >> 2;
    int qtr = blockIdx.x & 3;
    int b = bg >> 1, g = bg & 1;

    for (int i = tid; i < 1600; i += 1024) ws_sm[i] = w_dw[i];
    __syncthreads();

    for (int r = tid; r < 4096; r += 1024) {
        int c = r >> 6, spl = r & 63;
        int sp = qtr * 64 + spl;
        int i = sp >> 4, j = sp & 15;
        int y0 = 4 * i - 2, x0 = 4 * j - 2;
        const float* plane = g_q + ((size_t)(b * 128 + g * 64 + c)) * HW_;
        const float* ws = ws_sm + c * 25;
        float acc = 0.f;
#pragma unroll
        for (int u = 0; u < 5; u++) {
            int yy = y0 + u;
            if ((unsigned)yy < 64u) {
#pragma unroll
                for (int v = 0; v < 5; v++) {
                    int xx = x0 + v;
                    if ((unsigned)xx < 64u) acc += plane[yy * 64 + xx] * ws[u * 5 + v];
                }
            }
        }
        off_sm[c * 65 + spl] = acc;
    }
    __syncthreads();

    if (tid < 64) {
        int spl = tid;
        int sp = qtr * 64 + spl;
        float s = 0.f, s2 = 0.f;
#pragma unroll 8
        for (int c = 0; c < 64; c++) {
            float t = off_sm[c * 65 + spl];
            s += t; s2 += t * t;
        }
        float mean = s * (1.f / 64.f);
        float var  = s2 * (1.f / 64.f) - mean * mean;
        float rstd = rsqrtf(var + 1e-5f);
        float o0 = 0.f, o1 = 0.f, o2 = 0.f;
#pragma unroll 8
        for (int c = 0; c < 64; c++) {
            float t = off_sm[c * 65 + spl] * rstd * __ldg(&ln_w[c]);
            float ge = 0.5f * t * (1.f + erff(t * 0.70710678118654752f));
            o0 += __ldg(&w_off[c]) * ge;
            o1 += __ldg(&w_off[64 + c]) * ge;
            o2 += __ldg(&w_off[128 + c]) * ge;
        }
        int i = sp >> 4, j = sp & 15;
        float ry = (float)(2 * i + 1) * (1.f / 16.f) - 1.f;
        float rx = (float)(2 * j + 1) * (1.f / 16.f) - 1.f;
        float py = tanhf(o0) * (1.f / 16.f) + ry;
        float px = tanhf(o1) * (1.f / 16.f) + rx;
        pos_y[spl] = py;
        pos_x[spl] = px;
        dm_sm[spl] = 1.f / (1.f + expf(-o2));
        g_pos[bg * 512 + sp * 2]     = py;
        g_pos[bg * 512 + sp * 2 + 1] = px;
    }
    __syncthreads();

    for (int r = tid; r < 4096; r += 1024) {
        int c = r >> 6, spl = r & 63;
        int n = qtr * 64 + spl;
        const float* plane = x + ((size_t)(b * 128 + g * 64 + c)) * HW_;
        float gx = fminf((pos_x[spl] + 1.f) * 31.5f, 62.99999f);
        float gy = fminf((pos_y[spl] + 1.f) * 31.5f, 62.99999f);
        float x0f = floorf(gx), y0f = floorf(gy);
        float wx = gx - x0f, wy = gy - y0f;
        int ix0 = (int)x0f, iy0 = (int)y0f;
        const float* row0 = plane + iy0 * 64 + ix0;
        float v00 = row0[0], v01 = row0[1];
        float v10 = row0[64], v11 = row0[65];
        float top = v00 + (v01 - v00) * wx;
        float bot = v10 + (v11 - v10) * wx;
        float val = top + (bot - top) * wy;
        g_xs[((size_t)(b * 128 + g * 64 + c)) * NKV_ + n] = val * dm_sm[spl];
    }
}

// ---------------- fused attention v12: fp16 QK + fp16 PV ----------------
// smem layout (float indices)
#define SMC_RPE  0                        // 16129 (+3 pad), pre-scaled by log2e
#define SMC_KH   16132                    // [256 n][20] uint32 half2 channel-pairs
#define SMC_VH   (SMC_KH + 5120)          // [32 c][132] half2 of V key-pairs
#define SMC_PTH  (SMC_VH + 4224)          // [64 q][132] half2 of exp(scores) key-pairs
#define SMC_GTB  (SMC_PTH + 8448)         // [256] float4 {bx, wy0, wy1, packed rows}
#define SMC_RED  (SMC_GTB + 1024)         // [8][64] partial sums
#define SMC_QH   (SMC_RED + 512)          // [64 q][20] uint32 half2 channel-pairs (q*scale)
#define SMC_PS   (SMC_QH + 1280)          // psum [4][64][36]
#define ATTNC_FLOATS (SMC_PS + 9216)      // 45956 floats = 183824 B

#define LOG2E_ 1.4426950408889634f

__device__ __forceinline__ float bilin2(const float* __restrict__ rpe_sm,
                                        float gx, float wy0, float wy1,
                                        int r0, int r1)
{
    float x0f = floorf(gx);
    float wx = gx - x0f;
    int ix0 = (int)x0f;
    float v00 = rpe_sm[r0 + ix0], v01 = rpe_sm[r0 + ix0 + 1];
    float v10 = rpe_sm[r1 + ix0], v11 = rpe_sm[r1 + ix0 + 1];
    float t0 = v00 + (v01 - v00) * wx;
    float t1 = v10 + (v11 - v10) * wx;
    return t0 * wy0 + t1 * wy1;
}

__global__ void __launch_bounds__(1024) attn_kernel(const float* __restrict__ rpe,
                                                    float* __restrict__ outp, int nt)
{
    extern __shared__ float sm[];
    float* rpe_sm = sm + SMC_RPE;
    uint32_t* kh  = (uint32_t*)(sm + SMC_KH);
    uint32_t* vh  = (uint32_t*)(sm + SMC_VH);
    uint32_t* pth = (uint32_t*)(sm + SMC_PTH);
    float4* gtb   = (float4*)(sm + SMC_GTB);
    float* red    = sm + SMC_RED;
    uint32_t* qh  = (uint32_t*)(sm + SMC_QH);
    float* psum   = sm + SMC_PS;

    int tid = threadIdx.x;
    int bh    = blockIdx.x >> 4;
    int group = blockIdx.x & 15;
    int b = bh >> 2, h = bh & 3, g = h >> 1;

    // ---- per-head loads ----
    const float* rp = rpe + (size_t)h * RPE_N;
    for (int i = tid; i < RPE_N; i += 1024) rpe_sm[i] = rp[i] * LOG2E_;

    // k as half2 channel-pairs: kh[n][cp] = {K[2cp][n], K[2cp+1][n]}
    const float* kb = g_k + ((size_t)(b * 128 + h * 32)) * NKV_;
    for (int i = tid; i < 4096; i += 1024) {
        int cp = i >> 8, n = i & 255;
        kh[n * 20 + cp] = h2pack(kb[(2 * cp) * 256 + n], kb[(2 * cp + 1) * 256 + n]);
    }
    // V as half2 key-pairs: vh[c][np] = {V[c][2np], V[c][2np+1]}
    const float* vb = g_v + ((size_t)(b * 128 + h * 32)) * NKV_;
    for (int i = tid; i < 4096; i += 1024) {
        int c = i >> 7, np = i & 127;
        float2 v2 = *(const float2*)&vb[c * 256 + 2 * np];
        vh[c * 132 + np] = h2pack(v2.x, v2.y);
    }

    float ppy = 0.f, ppx = 0.f;
    if (tid < 256) {
        float2 p2 = ((const float2*)(g_pos + (size_t)(b * 2 + g) * 512))[tid];
        ppy = p2.x; ppx = p2.y;
    }

    int lane = tid & 31, w = tid >> 5;
    int r4 = lane >> 2, c4 = lane & 3;
    // QK mapping
    int mblk = w & 3;       // q block of 16
    int ngrp = w >> 2;      // n group of 32
    // PV mapping: 8 tiles (4 qb x 2 cb) x 4 k-quarters
    int pvt = w & 7, kq = w >> 3;
    int qm  = (pvt & 3) * 16;
    int cv0 = (pvt >> 2) * 16;

    const float scale2 = 0.17677669529663687f * LOG2E_;

    for (int t = 0; t < nt; t++) {
        int tile = group * 4 + t;
        int qbase = tile * 64;
        __syncthreads();   // protect pth/qh/gtb reuse across tiles

        // per-tile bias tables (y-half hoisted)
        if (tid < 256) {
            float qy315 = (float)(2 * tile + 1) * 0.4921875f - 31.5f;
            float gy = qy315 + 63.f - 31.5f * ppy;
            float bx = 63.f - 31.5f * ppx;
            float y0f = floorf(gy);
            float wy = gy - y0f;
            unsigned r0 = (unsigned)((int)y0f * 127);
            gtb[tid] = make_float4(bx, 1.f - wy, wy, __uint_as_float(r0 | ((r0 + 127) << 16)));
        }
        // q staged as half2 channel-pairs: qh[qi][cp] = {q[2cp][qi], q[2cp+1][qi]} * scale2
        {
            int cp = tid >> 6, qi = tid & 63;
            const float* qb = g_q + ((size_t)(b * 128 + h * 32)) * HW_ + qbase;
            float v0 = qb[(size_t)(2 * cp) * HW_ + qi] * scale2;
            float v1 = qb[(size_t)(2 * cp + 1) * HW_ + qi] * scale2;
            qh[qi * 20 + cp] = h2pack(v0, v1);
        }
        __syncthreads();

        // ---- QK via f16 mma (m16n8k16): warp = 16q x 32n x 32k ----
        float d[4][4];
#pragma unroll
        for (int i = 0; i < 4; i++)
#pragma unroll
            for (int j = 0; j < 4; j++) d[i][j] = 0.f;

        int qa = mblk * 16 + r4;
#pragma unroll
        for (int ks = 0; ks < 2; ks++) {
            int kp = ks * 8;   // channel-pair base (16 channels per step)
            uint32_t a0 = qh[qa * 20 + kp + c4];
            uint32_t a1 = qh[(qa + 8) * 20 + kp + c4];
            uint32_t a2 = qh[qa * 20 + kp + c4 + 4];
            uint32_t a3 = qh[(qa + 8) * 20 + kp + c4 + 4];
#pragma unroll
            for (int nb = 0; nb < 4; nb++) {
                int ncol = ngrp * 32 + nb * 8 + r4;
                uint32_t b0 = kh[ncol * 20 + kp + c4];
                uint32_t b1 = kh[ncol * 20 + kp + c4 + 4];
                mma_f16(d[nb], a0, a1, a2, a3, b0, b1);
            }
        }

        // ---- fused bias + exp2 + half2 store + partial sums ----
        {
            float axl = (float)(2 * (mblk * 16 + r4) + 1) * 0.4921875f - 31.5f;
            float axh = axl + 7.875f;
            float suml = 0.f, sumh = 0.f;
            int qrow = mblk * 16 + r4;
#pragma unroll
            for (int nb = 0; nb < 4; nb++) {
                int nn = ngrp * 32 + nb * 8 + 2 * c4;     // even key index
                float4 G0 = gtb[nn], G1 = gtb[nn + 1];
                uint32_t u0 = __float_as_uint(G0.w);
                uint32_t u1 = __float_as_uint(G1.w);
                int r00 = u0 & 0xffff, r01 = u0 >> 16;
                int r10 = u1 & 0xffff, r11 = u1 >> 16;
                float e0 = ex2f(d[nb][0] + bilin2(rpe_sm, axl + G0.x, G0.y, G0.z, r00, r01));
                float e1 = ex2f(d[nb][1] + bilin2(rpe_sm, axl + G1.x, G1.y, G1.z, r10, r11));
                float e2 = ex2f(d[nb][2] + bilin2(rpe_sm, axh + G0.x, G0.y, G0.z, r00, r01));
                float e3 = ex2f(d[nb][3] + bilin2(rpe_sm, axh + G1.x, G1.y, G1.z, r10, r11));
                suml += e0 + e1;
                sumh += e2 + e3;
                int npi = (nn >> 1);                      // ngrp*16 + nb*4 + c4
                pth[qrow * 132 + npi]       = h2pack(e0, e1);
                pth[(qrow + 8) * 132 + npi] = h2pack(e2, e3);
            }
            suml += __shfl_xor_sync(0xffffffffu, suml, 1);
            suml += __shfl_xor_sync(0xffffffffu, suml, 2);
            sumh += __shfl_xor_sync(0xffffffffu, sumh, 1);
            sumh += __shfl_xor_sync(0xffffffffu, sumh, 2);
            if (c4 == 0) {
                red[ngrp * 64 + qrow]     = suml;
                red[ngrp * 64 + qrow + 8] = sumh;
            }
        }
        __syncthreads();

        // ---- PV via f16 mma (m16n8k16): warp = 16q x 16c x 64k ----
        float dd0[4] = {0.f, 0.f, 0.f, 0.f};
        float dd1[4] = {0.f, 0.f, 0.f, 0.f};
#pragma unroll
        for (int ks = 0; ks < 4; ks++) {
            int koff = kq * 32 + ks * 8;                  // half2 index of key base
            uint32_t a0 = pth[(qm + r4) * 132 + koff + c4];
            uint32_t a1 = pth[(qm + 8 + r4) * 132 + koff + c4];
            uint32_t a2 = pth[(qm + r4) * 132 + koff + c4 + 4];
            uint32_t a3 = pth[(qm + 8 + r4) * 132 + koff + c4 + 4];
            uint32_t b0 = vh[(cv0 + r4) * 132 + koff + c4];
            uint32_t b1 = vh[(cv0 + r4) * 132 + koff + c4 + 4];
            uint32_t b2 = vh[(cv0 + 8 + r4) * 132 + koff + c4];
            uint32_t b3 = vh[(cv0 + 8 + r4) * 132 + koff + c4 + 4];
            mma_f16(dd0, a0, a1, a2, a3, b0, b1);
            mma_f16(dd1, a0, a1, a2, a3, b2, b3);
        }
        // psum has its own region: no sync needed before store
        {
            float* ps = psum + kq * 2304;
            *(float2*)&ps[(qm + r4) * 36 + cv0 + 2 * c4]         = make_float2(dd0[0], dd0[1]);
            *(float2*)&ps[(qm + 8 + r4) * 36 + cv0 + 2 * c4]     = make_float2(dd0[2], dd0[3]);
            *(float2*)&ps[(qm + r4) * 36 + cv0 + 8 + 2 * c4]     = make_float2(dd1[0], dd1[1]);
            *(float2*)&ps[(qm + 8 + r4) * 36 + cv0 + 8 + 2 * c4] = make_float2(dd1[2], dd1[3]);
        }
        __syncthreads();

        // ---- epilogue ----
        {
            int qq = tid & 63;
            int ci = tid >> 6;
            float tot = 0.f;
#pragma unroll
            for (int k = 0; k < 8; k++) tot += red[k * 64 + qq];
            float inv = 1.f / tot;
            float* ob = outp + ((size_t)(b * 128 + h * 32)) * HW_ + qbase + qq;
#pragma unroll
            for (int u = 0; u < 2; u++) {
                int cc = ci + u * 16;
                float sv = psum[qq * 36 + cc]
                         + psum[2304 + qq * 36 + cc]
                         + psum[4608 + qq * 36 + cc]
                         + psum[6912 + qq * 36 + cc];
                ob[(size_t)cc * HW_] = sv * inv;
            }
        }
    }
}

// ---------------- launch ----------------
extern "C" void kernel_launch(void* const* d_in, const int* in_sizes, int n_in,
                              void* d_out, int out_size)
{
    const float* x     = (const float*)d_in[0];
    const float* w_dw  = (const float*)d_in[1];
    const float* ln_w  = (const float*)d_in[2];
    const float* w_off = (const float*)d_in[3];
    const float* wq    = (const float*)d_in[4];
    const float* wk    = (const float*)d_in[5];
    const float* wv    = (const float*)d_in[6];
    const float* wo    = (const float*)d_in[7];
    const float* rpe   = (const float*)d_in[8];
    float* out = (float*)d_out;

    float *gq, *gao;
    cudaGetSymbolAddress((void**)&gq, g_q);
    cudaGetSymbolAddress((void**)&gao, g_ao);

    cudaFuncSetAttribute(gemm_tf32_kernel, cudaFuncAttributeMaxDynamicSharedMemorySize, GT_FLOATS * 4);
    cudaFuncSetAttribute(gemm_kv_tf32_kernel, cudaFuncAttributeMaxDynamicSharedMemorySize, GT_FLOATS * 4);
    cudaFuncSetAttribute(attn_kernel, cudaFuncAttributeMaxDynamicSharedMemorySize,
                         ATTNC_FLOATS * 4);

    // 1: q projection (tf32 mma)
    gemm_tf32_kernel<<<128, 1024, GT_FLOATS * 4>>>(wq, x, gq, HW_, 16);
    // 2: fused offset pipeline
    offset_kernel<<<64, 1024>>>(x, w_dw, ln_w, w_off);
    // 3: k/v projections (tf32 mma, outputs pre-rounded)
    gemm_kv_tf32_kernel<<<16, 1024, GT_FLOATS * 4>>>(wk, wv);
    // 4: fused attention (ncu capture slot)
    attn_kernel<<<512, 1024, ATTNC_FLOATS * 4>>>(rpe, gao, 4);
    // 5: output projection (tf32 mma)
    gemm_tf32_kernel<<<128, 1024, GT_FLOATS * 4>>>(wo, gao, out, HW_, 16);
}

// round 15
// speedup vs baseline: 1.6039x; 1.1781x over previous
#include <cuda_runtime.h>
#include <math.h>
#include <stdint.h>

// ---------------- problem constants ----------------
#define B_   8
#define C_   128
#define HW_  4096
#define NKV_ 256
#define RPE_N 16129     // 127*127

// ---------------- helpers ----------------
__device__ __forceinline__ float ex2f(float x) {
    float r;
    asm("ex2.approx.f32 %0, %1;" : "=f"(r) : "f"(x));
    return r;
}
__device__ __forceinline__ float tf32r(float x) {
    uint32_t u;
    asm("cvt.rna.tf32.f32 %0, %1;" : "=r"(u) : "f"(x));
    return __uint_as_float(u);
}
__device__ __forceinline__ uint32_t h2pack(float lo, float hi) {
    uint32_t r;
    asm("cvt.rn.f16x2.f32 %0, %1, %2;" : "=r"(r) : "f"(hi), "f"(lo));
    return r;
}
__device__ __forceinline__ void mma_tf32(float d[4],
    uint32_t a0, uint32_t a1, uint32_t a2, uint32_t a3,
    uint32_t b0, uint32_t b1)
{
    asm volatile(
        "mma.sync.aligned.m16n8k8.row.col.f32.tf32.tf32.f32 "
        "{%0,%1,%2,%3}, {%4,%5,%6,%7}, {%8,%9}, {%0,%1,%2,%3};"
        : "+f"(d[0]), "+f"(d[1]), "+f"(d[2]), "+f"(d[3])
        : "r"(a0), "r"(a1), "r"(a2), "r"(a3), "r"(b0), "r"(b1));
}
__device__ __forceinline__ void mma_f16(float d[4],
    uint32_t a0, uint32_t a1, uint32_t a2, uint32_t a3,
    uint32_t b0, uint32_t b1)
{
    asm volatile(
        "mma.sync.aligned.m16n8k16.row.col.f32.f16.f16.f32 "
        "{%0,%1,%2,%3}, {%4,%5,%6,%7}, {%8,%9}, {%0,%1,%2,%3};"
        : "+f"(d[0]), "+f"(d[1]), "+f"(d[2]), "+f"(d[3])
        : "r"(a0), "r"(a1), "r"(a2), "r"(a3), "r"(b0), "r"(b1));
}
#define FU(x) __float_as_uint(x)

// ---------------- device scratch ----------------
__device__ float g_q  [B_ * C_ * HW_];
__device__ float g_ao [B_ * C_ * HW_];
__device__ float g_pos[16 * NKV_ * 2];
__device__ float g_xs [B_ * C_ * NKV_];
__device__ float g_k  [B_ * C_ * NKV_];
__device__ float g_v  [B_ * C_ * NKV_];

// ---------------- tf32 mma GEMM (conflict-free addressing) ----------------
#define GT_FLOATS (16896 + 33792)   // 50688 floats = 202752 B

__device__ __forceinline__ void gemm_tf32_tile(
    const float* __restrict__ A, const float* __restrict__ Xb,
    float* __restrict__ Yb, int ld, int rnd)
{
    extern __shared__ float sm[];
    float* a_sm = sm;
    float* b_sm = sm + 16896;
    int tid = threadIdx.x;

    for (int i = tid; i < 4096; i += 1024) {
        int m = i >> 5, k0 = (i & 31) * 4;
        float4 v = *(const float4*)(A + m * 128 + k0);
        float* d = a_sm + m * 132 + k0;
        d[0] = tf32r(v.x); d[1] = tf32r(v.y); d[2] = tf32r(v.z); d[3] = tf32r(v.w);
    }
    for (int i = tid; i < 8192; i += 1024) {
        int k = i >> 6, n0 = (i & 63) * 4;
        float4 v = *(const float4*)(Xb + (size_t)k * ld + n0);
        float* d = b_sm + k * 264 + n0;
        d[0] = tf32r(v.x); d[1] = tf32r(v.y); d[2] = tf32r(v.z); d[3] = tf32r(v.w);
    }
    __syncthreads();

    int lane = tid & 31, w = tid >> 5;
    int r4 = lane >> 2, c4 = lane & 3;
    int mt = (w >> 3) * 32;
    int nt = (w & 7) * 32;

    float d[2][4][4];
#pragma unroll
    for (int s = 0; s < 2; s++)
#pragma unroll
        for (int nb = 0; nb < 4; nb++)
#pragma unroll
            for (int j = 0; j < 4; j++) d[s][nb][j] = 0.f;

#pragma unroll
    for (int ks = 0; ks < 16; ks++) {
        int kc = ks * 8 + c4;
        uint32_t a[2][4];
#pragma unroll
        for (int s = 0; s < 2; s++) {
            int qa = mt + s * 16 + r4;
            a[s][0] = FU(a_sm[qa * 132 + kc]);
            a[s][1] = FU(a_sm[(qa + 8) * 132 + kc]);
            a[s][2] = FU(a_sm[qa * 132 + kc + 4]);
            a[s][3] = FU(a_sm[(qa + 8) * 132 + kc + 4]);
        }
#pragma unroll
        for (int nb = 0; nb < 4; nb++) {
            int ncol = nt + nb * 8 + r4;
            uint32_t b0 = FU(b_sm[kc * 264 + ncol]);
            uint32_t b1 = FU(b_sm[(kc + 4) * 264 + ncol]);
            mma_tf32(d[0][nb], a[0][0], a[0][1], a[0][2], a[0][3], b0, b1);
            mma_tf32(d[1][nb], a[1][0], a[1][1], a[1][2], a[1][3], b0, b1);
        }
    }
#pragma unroll
    for (int s = 0; s < 2; s++)
#pragma unroll
        for (int nb = 0; nb < 4; nb++) {
            int m0 = mt + s * 16 + r4;
            int n0 = nt + nb * 8 + 2 * c4;
            float2 lo = make_float2(d[s][nb][0], d[s][nb][1]);
            float2 hi = make_float2(d[s][nb][2], d[s][nb][3]);
            if (rnd) {
                lo.x = tf32r(lo.x); lo.y = tf32r(lo.y);
                hi.x = tf32r(hi.x); hi.y = tf32r(hi.y);
            }
            *(float2*)(Yb + (size_t)m0 * ld + n0)       = lo;
            *(float2*)(Yb + (size_t)(m0 + 8) * ld + n0) = hi;
        }
}

__global__ void __launch_bounds__(1024) gemm_tf32_kernel(
    const float* __restrict__ A, const float* __restrict__ X,
    float* __restrict__ Y, int ld, int ntiles)
{
    int b  = blockIdx.x / ntiles;
    int pb = (blockIdx.x % ntiles) * 256;
    gemm_tf32_tile(A, X + (size_t)b * 128 * ld + pb, Y + (size_t)b * 128 * ld + pb, ld, 0);
}

__global__ void __launch_bounds__(1024) gemm_kv_tf32_kernel(
    const float* __restrict__ wk, const float* __restrict__ wv)
{
    int sel = blockIdx.x >> 3;
    int b   = blockIdx.x & 7;
    const float* A = sel ? wv : wk;
    float* Y = sel ? g_v : g_k;
    gemm_tf32_tile(A, g_xs + (size_t)b * 128 * NKV_, Y + (size_t)b * 128 * NKV_, NKV_, 1);
}

// ---------------- fused offset pipeline ----------------
__global__ void __launch_bounds__(1024) offset_kernel(
    const float* __restrict__ x, const float* __restrict__ w_dw,
    const float* __restrict__ ln_w, const float* __restrict__ w_off)
{
    __shared__ float off_sm[64 * 65];
    __shared__ float ws_sm[1600];
    __shared__ float pos_y[64], pos_x[64], dm_sm[64];

    int tid = threadIdx.x;
    int bg  = blockIdx.x >> 2;
    int qtr = blockIdx.x & 3;
    int b = bg >> 1, g = bg & 1;

    for (int i = tid; i < 1600; i += 1024) ws_sm[i] = w_dw[i];
    __syncthreads();

    for (int r = tid; r < 4096; r += 1024) {
        int c = r >> 6, spl = r & 63;
        int sp = qtr * 64 + spl;
        int i = sp >> 4, j = sp & 15;
        int y0 = 4 * i - 2, x0 = 4 * j - 2;
        const float* plane = g_q + ((size_t)(b * 128 + g * 64 + c)) * HW_;
        const float* ws = ws_sm + c * 25;
        float acc = 0.f;
#pragma unroll
        for (int u = 0; u < 5; u++) {
            int yy = y0 + u;
            if ((unsigned)yy < 64u) {
#pragma unroll
                for (int v = 0; v < 5; v++) {
                    int xx = x0 + v;
                    if ((unsigned)xx < 64u) acc += plane[yy * 64 + xx] * ws[u * 5 + v];
                }
            }
        }
        off_sm[c * 65 + spl] = acc;
    }
    __syncthreads();

    if (tid < 64) {
        int spl = tid;
        int sp = qtr * 64 + spl;
        float s = 0.f, s2 = 0.f;
#pragma unroll 8
        for (int c = 0; c < 64; c++) {
            float t = off_sm[c * 65 + spl];
            s += t; s2 += t * t;
        }
        float mean = s * (1.f / 64.f);
        float var  = s2 * (1.f / 64.f) - mean * mean;
        float rstd = rsqrtf(var + 1e-5f);
        float o0 = 0.f, o1 = 0.f, o2 = 0.f;
#pragma unroll 8
        for (int c = 0; c < 64; c++) {
            float t = off_sm[c * 65 + spl] * rstd * __ldg(&ln_w[c]);
            float ge = 0.5f * t * (1.f + erff(t * 0.70710678118654752f));
            o0 += __ldg(&w_off[c]) * ge;
            o1 += __ldg(&w_off[64 + c]) * ge;
            o2 += __ldg(&w_off[128 + c]) * ge;
        }
        int i = sp >> 4, j = sp & 15;
        float ry = (float)(2 * i + 1) * (1.f / 16.f) - 1.f;
        float rx = (float)(2 * j + 1) * (1.f / 16.f) - 1.f;
        float py = tanhf(o0) * (1.f / 16.f) + ry;
        float px = tanhf(o1) * (1.f / 16.f) + rx;
        pos_y[spl] = py;
        pos_x[spl] = px;
        dm_sm[spl] = 1.f / (1.f + expf(-o2));
        g_pos[bg * 512 + sp * 2]     = py;
        g_pos[bg * 512 + sp * 2 + 1] = px;
    }
    __syncthreads();

    for (int r = tid; r < 4096; r += 1024) {
        int c = r >> 6, spl = r & 63;
        int n = qtr * 64 + spl;
        const float* plane = x + ((size_t)(b * 128 + g * 64 + c)) * HW_;
        float gx = fminf((pos_x[spl] + 1.f) * 31.5f, 62.99999f);
        float gy = fminf((pos_y[spl] + 1.f) * 31.5f, 62.99999f);
        float x0f = floorf(gx), y0f = floorf(gy);
        float wx = gx - x0f, wy = gy - y0f;
        int ix0 = (int)x0f, iy0 = (int)y0f;
        const float* row0 = plane + iy0 * 64 + ix0;
        float v00 = row0[0], v01 = row0[1];
        float v10 = row0[64], v11 = row0[65];
        float top = v00 + (v01 - v00) * wx;
        float bot = v10 + (v11 - v10) * wx;
        float val = top + (bot - top) * wy;
        g_xs[((size_t)(b * 128 + g * 64 + c)) * NKV_ + n] = val * dm_sm[spl];
    }
}

// ---------------- fused attention v13: persistent, fp16 QK + fp16 PV ----------------
// smem layout (float indices)
#define SMC_RPE  0                        // 16129 (+3 pad), pre-scaled by log2e
#define SMC_KH   16132                    // [256 n][20] uint32 half2 channel-pairs
#define SMC_VH   (SMC_KH + 5120)          // [32 c][132] half2 of V key-pairs
#define SMC_PTH  (SMC_VH + 4224)          // [64 q][132] half2 of exp(scores) key-pairs
#define SMC_GTB  (SMC_PTH + 8448)         // [256] float4 {bx, wy0, wy1, packed rows}
#define SMC_RED  (SMC_GTB + 1024)         // [8][64] partial sums
#define SMC_QH   (SMC_RED + 512)          // [64 q][20] uint32 half2 channel-pairs (q*scale)
#define SMC_PS   (SMC_QH + 1280)          // psum [4][64][36]
#define ATTNC_FLOATS (SMC_PS + 9216)      // 45956 floats = 183824 B

#define LOG2E_ 1.4426950408889634f
#define NTILES_TOTAL 2048
#define NBLK 148

__device__ __forceinline__ float bilin2(const float* __restrict__ rpe_sm,
                                        float gx, float wy0, float wy1,
                                        int r0, int r1)
{
    float x0f = floorf(gx);
    float wx = gx - x0f;
    int ix0 = (int)x0f;
    float v00 = rpe_sm[r0 + ix0], v01 = rpe_sm[r0 + ix0 + 1];
    float v10 = rpe_sm[r1 + ix0], v11 = rpe_sm[r1 + ix0 + 1];
    float t0 = v00 + (v01 - v00) * wx;
    float t1 = v10 + (v11 - v10) * wx;
    return t0 * wy0 + t1 * wy1;
}

__global__ void __launch_bounds__(1024) attn_kernel(const float* __restrict__ rpe,
                                                    float* __restrict__ outp)
{
    extern __shared__ float sm[];
    float* rpe_sm = sm + SMC_RPE;
    uint32_t* kh  = (uint32_t*)(sm + SMC_KH);
    uint32_t* vh  = (uint32_t*)(sm + SMC_VH);
    uint32_t* pth = (uint32_t*)(sm + SMC_PTH);
    float4* gtb   = (float4*)(sm + SMC_GTB);
    float* red    = sm + SMC_RED;
    uint32_t* qh  = (uint32_t*)(sm + SMC_QH);
    float* psum   = sm + SMC_PS;

    int tid = threadIdx.x;
    int lane = tid & 31, w = tid >> 5;
    int r4 = lane >> 2, c4 = lane & 3;
    // QK mapping
    int mblk = w & 3;       // q block of 16
    int ngrp = w >> 2;      // n group of 32
    // PV mapping: 8 tiles (4 qb x 2 cb) x 4 k-quarters
    int pvt = w & 7, kq = w >> 3;
    int qm  = (pvt & 3) * 16;
    int cv0 = (pvt >> 2) * 16;

    const float scale2 = 0.17677669529663687f * LOG2E_;

    // persistent tile range (contiguous => <=2 head loads per block)
    int tstart = (int)(((long long)blockIdx.x * NTILES_TOTAL) / NBLK);
    int tend   = (int)(((long long)(blockIdx.x + 1) * NTILES_TOTAL) / NBLK);

    int cur_bh = -1;
    int b = 0, h = 0, g = 0;
    float ppy = 0.f, ppx = 0.f;

    for (int tg = tstart; tg < tend; tg++) {
        int bh   = tg >> 6;
        int tile = tg & 63;
        int qbase = tile * 64;

        if (bh != cur_bh) {
            // Safe without extra barrier: previous tile's psum-sync ordered all
            // reads of rpe/kh/vh; the staging sync below orders these writes
            // before this tile's compute.
            cur_bh = bh;
            b = bh >> 2; h = bh & 3; g = h >> 1;

            const float* rp = rpe + (size_t)h * RPE_N;
            for (int i = tid; i < RPE_N; i += 1024) rpe_sm[i] = rp[i] * LOG2E_;

            const float* kb = g_k + ((size_t)(b * 128 + h * 32)) * NKV_;
            for (int i = tid; i < 4096; i += 1024) {
                int cp = i >> 8, n = i & 255;
                kh[n * 20 + cp] = h2pack(kb[(2 * cp) * 256 + n], kb[(2 * cp + 1) * 256 + n]);
            }
            const float* vb = g_v + ((size_t)(b * 128 + h * 32)) * NKV_;
            for (int i = tid; i < 4096; i += 1024) {
                int c = i >> 7, np = i & 127;
                float2 v2 = *(const float2*)&vb[c * 256 + 2 * np];
                vh[c * 132 + np] = h2pack(v2.x, v2.y);
            }
            if (tid < 256) {
                float2 p2 = ((const float2*)(g_pos + (size_t)(b * 2 + g) * 512))[tid];
                ppy = p2.x; ppx = p2.y;
            }
        }

        // per-tile bias tables (y-half hoisted)
        if (tid < 256) {
            float qy315 = (float)(2 * tile + 1) * 0.4921875f - 31.5f;
            float gy = qy315 + 63.f - 31.5f * ppy;
            float bx = 63.f - 31.5f * ppx;
            float y0f = floorf(gy);
            float wy = gy - y0f;
            unsigned r0 = (unsigned)((int)y0f * 127);
            gtb[tid] = make_float4(bx, 1.f - wy, wy, __uint_as_float(r0 | ((r0 + 127) << 16)));
        }
        // q staged as half2 channel-pairs
        {
            int cp = tid >> 6, qi = tid & 63;
            const float* qb = g_q + ((size_t)(b * 128 + h * 32)) * HW_ + qbase;
            float v0 = qb[(size_t)(2 * cp) * HW_ + qi] * scale2;
            float v1 = qb[(size_t)(2 * cp + 1) * HW_ + qi] * scale2;
            qh[qi * 20 + cp] = h2pack(v0, v1);
        }
        __syncthreads();

        // ---- QK via f16 mma (m16n8k16): warp = 16q x 32n x 32k ----
        float d[4][4];
#pragma unroll
        for (int i = 0; i < 4; i++)
#pragma unroll
            for (int j = 0; j < 4; j++) d[i][j] = 0.f;

        int qa = mblk * 16 + r4;
#pragma unroll
        for (int ks = 0; ks < 2; ks++) {
            int kp = ks * 8;
            uint32_t a0 = qh[qa * 20 + kp + c4];
            uint32_t a1 = qh[(qa + 8) * 20 + kp + c4];
            uint32_t a2 = qh[qa * 20 + kp + c4 + 4];
            uint32_t a3 = qh[(qa + 8) * 20 + kp + c4 + 4];
#pragma unroll
            for (int nb = 0; nb < 4; nb++) {
                int ncol = ngrp * 32 + nb * 8 + r4;
                uint32_t b0 = kh[ncol * 20 + kp + c4];
                uint32_t b1 = kh[ncol * 20 + kp + c4 + 4];
                mma_f16(d[nb], a0, a1, a2, a3, b0, b1);
            }
        }

        // ---- fused bias + exp2 + half2 store + partial sums ----
        {
            float axl = (float)(2 * (mblk * 16 + r4) + 1) * 0.4921875f - 31.5f;
            float axh = axl + 7.875f;
            float suml = 0.f, sumh = 0.f;
            int qrow = mblk * 16 + r4;
#pragma unroll
            for (int nb = 0; nb < 4; nb++) {
                int nn = ngrp * 32 + nb * 8 + 2 * c4;
                float4 G0 = gtb[nn], G1 = gtb[nn + 1];
                uint32_t u0 = __float_as_uint(G0.w);
                uint32_t u1 = __float_as_uint(G1.w);
                int r00 = u0 & 0xffff, r01 = u0 >> 16;
                int r10 = u1 & 0xffff, r11 = u1 >> 16;
                float e0 = ex2f(d[nb][0] + bilin2(rpe_sm, axl + G0.x, G0.y, G0.z, r00, r01));
                float e1 = ex2f(d[nb][1] + bilin2(rpe_sm, axl + G1.x, G1.y, G1.z, r10, r11));
                float e2 = ex2f(d[nb][2] + bilin2(rpe_sm, axh + G0.x, G0.y, G0.z, r00, r01));
                float e3 = ex2f(d[nb][3] + bilin2(rpe_sm, axh + G1.x, G1.y, G1.z, r10, r11));
                suml += e0 + e1;
                sumh += e2 + e3;
                int npi = (nn >> 1);
                pth[qrow * 132 + npi]       = h2pack(e0, e1);
                pth[(qrow + 8) * 132 + npi] = h2pack(e2, e3);
            }
            suml += __shfl_xor_sync(0xffffffffu, suml, 1);
            suml += __shfl_xor_sync(0xffffffffu, suml, 2);
            sumh += __shfl_xor_sync(0xffffffffu, sumh, 1);
            sumh += __shfl_xor_sync(0xffffffffu, sumh, 2);
            if (c4 == 0) {
                red[ngrp * 64 + qrow]     = suml;
                red[ngrp * 64 + qrow + 8] = sumh;
            }
        }
        __syncthreads();

        // ---- PV via f16 mma (m16n8k16): warp = 16q x 16c x 64k ----
        float dd0[4] = {0.f, 0.f, 0.f, 0.f};
        float dd1[4] = {0.f, 0.f, 0.f, 0.f};
#pragma unroll
        for (int ks = 0; ks < 4; ks++) {
            int koff = kq * 32 + ks * 8;
            uint32_t a0 = pth[(qm + r4) * 132 + koff + c4];
            uint32_t a1 = pth[(qm + 8 + r4) * 132 + koff + c4];
            uint32_t a2 = pth[(qm + r4) * 132 + koff + c4 + 4];
            uint32_t a3 = pth[(qm + 8 + r4) * 132 + koff + c4 + 4];
            uint32_t b0 = vh[(cv0 + r4) * 132 + koff + c4];
            uint32_t b1 = vh[(cv0 + r4) * 132 + koff + c4 + 4];
            uint32_t b2 = vh[(cv0 + 8 + r4) * 132 + koff + c4];
            uint32_t b3 = vh[(cv0 + 8 + r4) * 132 + koff + c4 + 4];
            mma_f16(dd0, a0, a1, a2, a3, b0, b1);
            mma_f16(dd1, a0, a1, a2, a3, b2, b3);
        }
        {
            float* ps = psum + kq * 2304;
            *(float2*)&ps[(qm + r4) * 36 + cv0 + 2 * c4]         = make_float2(dd0[0], dd0[1]);
            *(float2*)&ps[(qm + 8 + r4) * 36 + cv0 + 2 * c4]     = make_float2(dd0[2], dd0[3]);
            *(float2*)&ps[(qm + r4) * 36 + cv0 + 8 + 2 * c4]     = make_float2(dd1[0], dd1[1]);
            *(float2*)&ps[(qm + 8 + r4) * 36 + cv0 + 8 + 2 * c4] = make_float2(dd1[2], dd1[3]);
        }
        __syncthreads();

        // ---- epilogue ----
        {
            int qq = tid & 63;
            int ci = tid >> 6;
            float tot = 0.f;
#pragma unroll
            for (int k = 0; k < 8; k++) tot += red[k * 64 + qq];
            float inv = 1.f / tot;
            float* ob = outp + ((size_t)(b * 128 + h * 32)) * HW_ + qbase + qq;
#pragma unroll
            for (int u = 0; u < 2; u++) {
                int cc = ci + u * 16;
                float sv = psum[qq * 36 + cc]
                         + psum[2304 + qq * 36 + cc]
                         + psum[4608 + qq * 36 + cc]
                         + psum[6912 + qq * 36 + cc];
                ob[(size_t)cc * HW_] = sv * inv;
            }
        }
    }
}

// ---------------- launch ----------------
extern "C" void kernel_launch(void* const* d_in, const int* in_sizes, int n_in,
                              void* d_out, int out_size)
{
    const float* x     = (const float*)d_in[0];
    const float* w_dw  = (const float*)d_in[1];
    const float* ln_w  = (const float*)d_in[2];
    const float* w_off = (const float*)d_in[3];
    const float* wq    = (const float*)d_in[4];
    const float* wk    = (const float*)d_in[5];
    const float* wv    = (const float*)d_in[6];
    const float* wo    = (const float*)d_in[7];
    const float* rpe   = (const float*)d_in[8];
    float* out = (float*)d_out;

    float *gq, *gao;
    cudaGetSymbolAddress((void**)&gq, g_q);
    cudaGetSymbolAddress((void**)&gao, g_ao);

    cudaFuncSetAttribute(gemm_tf32_kernel, cudaFuncAttributeMaxDynamicSharedMemorySize, GT_FLOATS * 4);
    cudaFuncSetAttribute(gemm_kv_tf32_kernel, cudaFuncAttributeMaxDynamicSharedMemorySize, GT_FLOATS * 4);
    cudaFuncSetAttribute(attn_kernel, cudaFuncAttributeMaxDynamicSharedMemorySize,
                         ATTNC_FLOATS * 4);

    // 1: q projection (tf32 mma)
    gemm_tf32_kernel<<<128, 1024, GT_FLOATS * 4>>>(wq, x, gq, HW_, 16);
    // 2: fused offset pipeline
    offset_kernel<<<64, 1024>>>(x, w_dw, ln_w, w_off);
    // 3: k/v projections (tf32 mma, outputs pre-rounded)
    gemm_kv_tf32_kernel<<<16, 1024, GT_FLOATS * 4>>>(wk, wv);
    // 4: fused attention — persistent, single wave (ncu capture slot)
    attn_kernel<<<NBLK, 1024, ATTNC_FLOATS * 4>>>(rpe, gao);
    // 5: output projection (tf32 mma)
    gemm_tf32_kernel<<<128, 1024, GT_FLOATS * 4>>>(wo, gao, out, HW_, 16);
}

// round 16
// speedup vs baseline: 1.7136x; 1.0684x over previous
#include <cuda_runtime.h>
#include <cuda_fp16.h>
#include <math.h>
#include <stdint.h>

// ---------------- problem constants ----------------
#define B_   8
#define C_   128
#define HW_  4096
#define NKV_ 256
#define RPE_N 16129     // 127*127

// ---------------- helpers ----------------
__device__ __forceinline__ float ex2f(float x) {
    float r;
    asm("ex2.approx.f32 %0, %1;" : "=f"(r) : "f"(x));
    return r;
}
__device__ __forceinline__ uint32_t h2pack(float lo, float hi) {
    uint32_t r;
    asm("cvt.rn.f16x2.f32 %0, %1, %2;" : "=r"(r) : "f"(hi), "f"(lo));
    return r;
}
__device__ __forceinline__ void mma_f16(float d[4],
    uint32_t a0, uint32_t a1, uint32_t a2, uint32_t a3,
    uint32_t b0, uint32_t b1)
{
    asm volatile(
        "mma.sync.aligned.m16n8k16.row.col.f32.f16.f16.f32 "
        "{%0,%1,%2,%3}, {%4,%5,%6,%7}, {%8,%9}, {%0,%1,%2,%3};"
        : "+f"(d[0]), "+f"(d[1]), "+f"(d[2]), "+f"(d[3])
        : "r"(a0), "r"(a1), "r"(a2), "r"(a3), "r"(b0), "r"(b1));
}
#define FU(x) __float_as_uint(x)

// ---------------- device scratch ----------------
__device__ float g_q  [B_ * C_ * HW_];
__device__ float g_ao [B_ * C_ * HW_];
__device__ float g_pos[16 * NKV_ * 2];
__device__ float g_xs [B_ * C_ * NKV_];
__device__ float g_k  [B_ * C_ * NKV_];
__device__ float g_v  [B_ * C_ * NKV_];

// ---------------- fp16 mma GEMM: Y[128, 256-tile] = A[128x128] * X ----------------
// A as [m][kpair] stride 68 (frag addr 4r4+c4: conflict-free)
// B as [kpair][n] stride 264 (frag addr 8c4+r4: conflict-free; STS/LDG coalesced)
#define GH_U32_A 8704     // 128 * 68
#define GH_U32_B 16896    // 64 * 264
#define GH_BYTES ((GH_U32_A + GH_U32_B) * 4)   // 102400 B

__device__ __forceinline__ void gemm_f16_tile(
    const float* __restrict__ A, const float* __restrict__ Xb,
    float* __restrict__ Yb, int ld)
{
    extern __shared__ float sm[];
    uint32_t* ah = (uint32_t*)sm;
    uint32_t* bhh = ah + GH_U32_A;
    int tid = threadIdx.x;

    for (int i = tid; i < 8192; i += 1024) {
        int m = i >> 6, kp = i & 63;
        float2 v = *(const float2*)(A + m * 128 + 2 * kp);
        ah[m * 68 + kp] = h2pack(v.x, v.y);
    }
    for (int i = tid; i < 16384; i += 1024) {
        int kp = i >> 8, n = i & 255;
        bhh[kp * 264 + n] = h2pack(Xb[(size_t)(2 * kp) * ld + n],
                                   Xb[(size_t)(2 * kp + 1) * ld + n]);
    }
    __syncthreads();

    int lane = tid & 31, w = tid >> 5;
    int r4 = lane >> 2, c4 = lane & 3;
    int mt = (w >> 3) * 32;
    int nt = (w & 7) * 32;

    float d[2][4][4];
#pragma unroll
    for (int s = 0; s < 2; s++)
#pragma unroll
        for (int nb = 0; nb < 4; nb++)
#pragma unroll
            for (int j = 0; j < 4; j++) d[s][nb][j] = 0.f;

#pragma unroll
    for (int ks = 0; ks < 8; ks++) {
        int kp = ks * 8;
        uint32_t a[2][4];
#pragma unroll
        for (int s = 0; s < 2; s++) {
            int qa = mt + s * 16 + r4;
            a[s][0] = ah[qa * 68 + kp + c4];
            a[s][1] = ah[(qa + 8) * 68 + kp + c4];
            a[s][2] = ah[qa * 68 + kp + c4 + 4];
            a[s][3] = ah[(qa + 8) * 68 + kp + c4 + 4];
        }
#pragma unroll
        for (int nb = 0; nb < 4; nb++) {
            int ncol = nt + nb * 8 + r4;
            uint32_t b0 = bhh[(kp + c4) * 264 + ncol];
            uint32_t b1 = bhh[(kp + c4 + 4) * 264 + ncol];
            mma_f16(d[0][nb], a[0][0], a[0][1], a[0][2], a[0][3], b0, b1);
            mma_f16(d[1][nb], a[1][0], a[1][1], a[1][2], a[1][3], b0, b1);
        }
    }
#pragma unroll
    for (int s = 0; s < 2; s++)
#pragma unroll
        for (int nb = 0; nb < 4; nb++) {
            int m0 = mt + s * 16 + r4;
            int n0 = nt + nb * 8 + 2 * c4;
            *(float2*)(Yb + (size_t)m0 * ld + n0)       = make_float2(d[s][nb][0], d[s][nb][1]);
            *(float2*)(Yb + (size_t)(m0 + 8) * ld + n0) = make_float2(d[s][nb][2], d[s][nb][3]);
        }
}

__global__ void __launch_bounds__(1024) gemm_f16_kernel(
    const float* __restrict__ A, const float* __restrict__ X,
    float* __restrict__ Y, int ld, int ntiles)
{
    int b  = blockIdx.x / ntiles;
    int pb = (blockIdx.x % ntiles) * 256;
    gemm_f16_tile(A, X + (size_t)b * 128 * ld + pb, Y + (size_t)b * 128 * ld + pb, ld);
}

__global__ void __launch_bounds__(1024) gemm_kv_f16_kernel(
    const float* __restrict__ wk, const float* __restrict__ wv)
{
    int sel = blockIdx.x >> 3;
    int b   = blockIdx.x & 7;
    const float* A = sel ? wv : wk;
    float* Y = sel ? g_v : g_k;
    gemm_f16_tile(A, g_xs + (size_t)b * 128 * NKV_, Y + (size_t)b * 128 * NKV_, NKV_);
}

// ---------------- fused offset pipeline ----------------
__global__ void __launch_bounds__(1024) offset_kernel(
    const float* __restrict__ x, const float* __restrict__ w_dw,
    const float* __restrict__ ln_w, const float* __restrict__ w_off)
{
    __shared__ float off_sm[64 * 65];
    __shared__ float ws_sm[1600];
    __shared__ float pos_y[64], pos_x[64], dm_sm[64];

    int tid = threadIdx.x;
    int bg  = blockIdx.x >> 2;
    int qtr = blockIdx.x & 3;
    int b = bg >> 1, g = bg & 1;

    for (int i = tid; i < 1600; i += 1024) ws_sm[i] = w_dw[i];
    __syncthreads();

    for (int r = tid; r < 4096; r += 1024) {
        int c = r >> 6, spl = r & 63;
        int sp = qtr * 64 + spl;
        int i = sp >> 4, j = sp & 15;
        int y0 = 4 * i - 2, x0 = 4 * j - 2;
        const float* plane = g_q + ((size_t)(b * 128 + g * 64 + c)) * HW_;
        const float* ws = ws_sm + c * 25;
        float acc = 0.f;
#pragma unroll
        for (int u = 0; u < 5; u++) {
            int yy = y0 + u;
            if ((unsigned)yy < 64u) {
#pragma unroll
                for (int v = 0; v < 5; v++) {
                    int xx = x0 + v;
                    if ((unsigned)xx < 64u) acc += plane[yy * 64 + xx] * ws[u * 5 + v];
                }
            }
        }
        off_sm[c * 65 + spl] = acc;
    }
    __syncthreads();

    if (tid < 64) {
        int spl = tid;
        int sp = qtr * 64 + spl;
        float s = 0.f, s2 = 0.f;
#pragma unroll 8
        for (int c = 0; c < 64; c++) {
            float t = off_sm[c * 65 + spl];
            s += t; s2 += t * t;
        }
        float mean = s * (1.f / 64.f);
        float var  = s2 * (1.f / 64.f) - mean * mean;
        float rstd = rsqrtf(var + 1e-5f);
        float o0 = 0.f, o1 = 0.f, o2 = 0.f;
#pragma unroll 8
        for (int c = 0; c < 64; c++) {
            float t = off_sm[c * 65 + spl] * rstd * __ldg(&ln_w[c]);
            float ge = 0.5f * t * (1.f + erff(t * 0.70710678118654752f));
            o0 += __ldg(&w_off[c]) * ge;
            o1 += __ldg(&w_off[64 + c]) * ge;
            o2 += __ldg(&w_off[128 + c]) * ge;
        }
        int i = sp >> 4, j = sp & 15;
        float ry = (float)(2 * i + 1) * (1.f / 16.f) - 1.f;
        float rx = (float)(2 * j + 1) * (1.f / 16.f) - 1.f;
        float py = tanhf(o0) * (1.f / 16.f) + ry;
        float px = tanhf(o1) * (1.f / 16.f) + rx;
        pos_y[spl] = py;
        pos_x[spl] = px;
        dm_sm[spl] = 1.f / (1.f + expf(-o2));
        g_pos[bg * 512 + sp * 2]     = py;
        g_pos[bg * 512 + sp * 2 + 1] = px;
    }
    __syncthreads();

    for (int r = tid; r < 4096; r += 1024) {
        int c = r >> 6, spl = r & 63;
        int n = qtr * 64 + spl;
        const float* plane = x + ((size_t)(b * 128 + g * 64 + c)) * HW_;
        float gx = fminf((pos_x[spl] + 1.f) * 31.5f, 62.99999f);
        float gy = fminf((pos_y[spl] + 1.f) * 31.5f, 62.99999f);
        float x0f = floorf(gx), y0f = floorf(gy);
        float wx = gx - x0f, wy = gy - y0f;
        int ix0 = (int)x0f, iy0 = (int)y0f;
        const float* row0 = plane + iy0 * 64 + ix0;
        float v00 = row0[0], v01 = row0[1];
        float v10 = row0[64], v11 = row0[65];
        float top = v00 + (v01 - v00) * wx;
        float bot = v10 + (v11 - v10) * wx;
        float val = top + (bot - top) * wy;
        g_xs[((size_t)(b * 128 + g * 64 + c)) * NKV_ + n] = val * dm_sm[spl];
    }
}

// ---------------- fused attention v14: persistent + half2 rpe ----------------
// smem layout (float indices)
#define SMC_RPE  0                        // 16129 uint32 half2 pairs (+3 pad)
#define SMC_KH   16132                    // [256 n][20] uint32 half2 channel-pairs
#define SMC_VH   (SMC_KH + 5120)          // [32 c][132] half2 of V key-pairs
#define SMC_PTH  (SMC_VH + 4224)          // [64 q][132] half2 of exp(scores) key-pairs
#define SMC_GTB  (SMC_PTH + 8448)         // [256] float4 {bx, wy0, wy1, packed rows}
#define SMC_RED  (SMC_GTB + 1024)         // [8][64] partial sums
#define SMC_QH   (SMC_RED + 512)          // [64 q][20] uint32 half2 channel-pairs (q*scale)
#define SMC_PS   (SMC_QH + 1280)          // psum [4][64][36]
#define ATTNC_FLOATS (SMC_PS + 9216)      // 45956 floats = 183824 B

#define LOG2E_ 1.4426950408889634f
#define NTILES_TOTAL 2048
#define NBLK 148

// x-only bilinear over half2-paired rpe: one LDS.32 per row (both x-taps)
__device__ __forceinline__ float bilin2h(const uint32_t* __restrict__ rpe_h2,
                                         float gx, float wy0, float wy1,
                                         int r0, int r1)
{
    float x0f = floorf(gx);
    float wx = gx - x0f;
    int ix0 = (int)x0f;
    float2 v0 = __half22float2(*(const __half2*)&rpe_h2[r0 + ix0]);
    float2 v1 = __half22float2(*(const __half2*)&rpe_h2[r1 + ix0]);
    float t0 = v0.x + (v0.y - v0.x) * wx;
    float t1 = v1.x + (v1.y - v1.x) * wx;
    return t0 * wy0 + t1 * wy1;
}

__global__ void __launch_bounds__(1024) attn_kernel(const float* __restrict__ rpe,
                                                    float* __restrict__ outp)
{
    extern __shared__ float sm[];
    uint32_t* rpe_h2 = (uint32_t*)(sm + SMC_RPE);
    uint32_t* kh  = (uint32_t*)(sm + SMC_KH);
    uint32_t* vh  = (uint32_t*)(sm + SMC_VH);
    uint32_t* pth = (uint32_t*)(sm + SMC_PTH);
    float4* gtb   = (float4*)(sm + SMC_GTB);
    float* red    = sm + SMC_RED;
    uint32_t* qh  = (uint32_t*)(sm + SMC_QH);
    float* psum   = sm + SMC_PS;

    int tid = threadIdx.x;
    int lane = tid & 31, w = tid >> 5;
    int r4 = lane >> 2, c4 = lane & 3;
    int mblk = w & 3;
    int ngrp = w >> 2;
    int pvt = w & 7, kq = w >> 3;
    int qm  = (pvt & 3) * 16;
    int cv0 = (pvt >> 2) * 16;

    const float scale2 = 0.17677669529663687f * LOG2E_;

    int tstart = (int)(((long long)blockIdx.x * NTILES_TOTAL) / NBLK);
    int tend   = (int)(((long long)(blockIdx.x + 1) * NTILES_TOTAL) / NBLK);

    int cur_bh = -1;
    int b = 0, h = 0, g = 0;
    float ppy = 0.f, ppx = 0.f;

    for (int tg = tstart; tg < tend; tg++) {
        int bh   = tg >> 6;
        int tile = tg & 63;
        int qbase = tile * 64;

        if (bh != cur_bh) {
            cur_bh = bh;
            b = bh >> 2; h = bh & 3; g = h >> 1;

            const float* rp = rpe + (size_t)h * RPE_N;
            for (int i = tid; i < RPE_N; i += 1024) {
                float cur = rp[i] * LOG2E_;
                float nxt = (i + 1 < RPE_N) ? rp[i + 1] * LOG2E_ : 0.f;
                rpe_h2[i] = h2pack(cur, nxt);
            }
            const float* kb = g_k + ((size_t)(b * 128 + h * 32)) * NKV_;
            for (int i = tid; i < 4096; i += 1024) {
                int cp = i >> 8, n = i & 255;
                kh[n * 20 + cp] = h2pack(kb[(2 * cp) * 256 + n], kb[(2 * cp + 1) * 256 + n]);
            }
            const float* vb = g_v + ((size_t)(b * 128 + h * 32)) * NKV_;
            for (int i = tid; i < 4096; i += 1024) {
                int c = i >> 7, np = i & 127;
                float2 v2 = *(const float2*)&vb[c * 256 + 2 * np];
                vh[c * 132 + np] = h2pack(v2.x, v2.y);
            }
            if (tid < 256) {
                float2 p2 = ((const float2*)(g_pos + (size_t)(b * 2 + g) * 512))[tid];
                ppy = p2.x; ppx = p2.y;
            }
        }

        // per-tile bias tables (y-half hoisted)
        if (tid < 256) {
            float qy315 = (float)(2 * tile + 1) * 0.4921875f - 31.5f;
            float gy = qy315 + 63.f - 31.5f * ppy;
            float bx = 63.f - 31.5f * ppx;
            float y0f = floorf(gy);
            float wy = gy - y0f;
            unsigned r0 = (unsigned)((int)y0f * 127);
            gtb[tid] = make_float4(bx, 1.f - wy, wy, __uint_as_float(r0 | ((r0 + 127) << 16)));
        }
        // q staged as half2 channel-pairs
        {
            int cp = tid >> 6, qi = tid & 63;
            const float* qb = g_q + ((size_t)(b * 128 + h * 32)) * HW_ + qbase;
            float v0 = qb[(size_t)(2 * cp) * HW_ + qi] * scale2;
            float v1 = qb[(size_t)(2 * cp + 1) * HW_ + qi] * scale2;
            qh[qi * 20 + cp] = h2pack(v0, v1);
        }
        __syncthreads();

        // ---- QK via f16 mma (m16n8k16): warp = 16q x 32n x 32k ----
        float d[4][4];
#pragma unroll
        for (int i = 0; i < 4; i++)
#pragma unroll
            for (int j = 0; j < 4; j++) d[i][j] = 0.f;

        int qa = mblk * 16 + r4;
#pragma unroll
        for (int ks = 0; ks < 2; ks++) {
            int kp = ks * 8;
            uint32_t a0 = qh[qa * 20 + kp + c4];
            uint32_t a1 = qh[(qa + 8) * 20 + kp + c4];
            uint32_t a2 = qh[qa * 20 + kp + c4 + 4];
            uint32_t a3 = qh[(qa + 8) * 20 + kp + c4 + 4];
#pragma unroll
            for (int nb = 0; nb < 4; nb++) {
                int ncol = ngrp * 32 + nb * 8 + r4;
                uint32_t b0 = kh[ncol * 20 + kp + c4];
                uint32_t b1 = kh[ncol * 20 + kp + c4 + 4];
                mma_f16(d[nb], a0, a1, a2, a3, b0, b1);
            }
        }

        // ---- fused bias + exp2 + half2 store + partial sums ----
        {
            float axl = (float)(2 * (mblk * 16 + r4) + 1) * 0.4921875f - 31.5f;
            float axh = axl + 7.875f;
            float suml = 0.f, sumh = 0.f;
            int qrow = mblk * 16 + r4;
#pragma unroll
            for (int nb = 0; nb < 4; nb++) {
                int nn = ngrp * 32 + nb * 8 + 2 * c4;
                float4 G0 = gtb[nn], G1 = gtb[nn + 1];
                uint32_t u0 = __float_as_uint(G0.w);
                uint32_t u1 = __float_as_uint(G1.w);
                int r00 = u0 & 0xffff, r01 = u0 >> 16;
                int r10 = u1 & 0xffff, r11 = u1 >> 16;
                float e0 = ex2f(d[nb][0] + bilin2h(rpe_h2, axl + G0.x, G0.y, G0.z, r00, r01));
                float e1 = ex2f(d[nb][1] + bilin2h(rpe_h2, axl + G1.x, G1.y, G1.z, r10, r11));
                float e2 = ex2f(d[nb][2] + bilin2h(rpe_h2, axh + G0.x, G0.y, G0.z, r00, r01));
                float e3 = ex2f(d[nb][3] + bilin2h(rpe_h2, axh + G1.x, G1.y, G1.z, r10, r11));
                suml += e0 + e1;
                sumh += e2 + e3;
                int npi = (nn >> 1);
                pth[qrow * 132 + npi]       = h2pack(e0, e1);
                pth[(qrow + 8) * 132 + npi] = h2pack(e2, e3);
            }
            suml += __shfl_xor_sync(0xffffffffu, suml, 1);
            suml += __shfl_xor_sync(0xffffffffu, suml, 2);
            sumh += __shfl_xor_sync(0xffffffffu, sumh, 1);
            sumh += __shfl_xor_sync(0xffffffffu, sumh, 2);
            if (c4 == 0) {
                red[ngrp * 64 + qrow]     = suml;
                red[ngrp * 64 + qrow + 8] = sumh;
            }
        }
        __syncthreads();

        // ---- PV via f16 mma (m16n8k16): warp = 16q x 16c x 64k ----
        float dd0[4] = {0.f, 0.f, 0.f, 0.f};
        float dd1[4] = {0.f, 0.f, 0.f, 0.f};
#pragma unroll
        for (int ks = 0; ks < 4; ks++) {
            int koff = kq * 32 + ks * 8;
            uint32_t a0 = pth[(qm + r4) * 132 + koff + c4];
            uint32_t a1 = pth[(qm + 8 + r4) * 132 + koff + c4];
            uint32_t a2 = pth[(qm + r4) * 132 + koff + c4 + 4];
            uint32_t a3 = pth[(qm + 8 + r4) * 132 + koff + c4 + 4];
            uint32_t b0 = vh[(cv0 + r4) * 132 + koff + c4];
            uint32_t b1 = vh[(cv0 + r4) * 132 + koff + c4 + 4];
            uint32_t b2 = vh[(cv0 + 8 + r4) * 132 + koff + c4];
            uint32_t b3 = vh[(cv0 + 8 + r4) * 132 + koff + c4 + 4];
            mma_f16(dd0, a0, a1, a2, a3, b0, b1);
            mma_f16(dd1, a0, a1, a2, a3, b2, b3);
        }
        {
            float* ps = psum + kq * 2304;
            *(float2*)&ps[(qm + r4) * 36 + cv0 + 2 * c4]         = make_float2(dd0[0], dd0[1]);
            *(float2*)&ps[(qm + 8 + r4) * 36 + cv0 + 2 * c4]     = make_float2(dd0[2], dd0[3]);
            *(float2*)&ps[(qm + r4) * 36 + cv0 + 8 + 2 * c4]     = make_float2(dd1[0], dd1[1]);
            *(float2*)&ps[(qm + 8 + r4) * 36 + cv0 + 8 + 2 * c4] = make_float2(dd1[2], dd1[3]);
        }
        __syncthreads();

        // ---- epilogue ----
        {
            int qq = tid & 63;
            int ci = tid >> 6;
            float tot = 0.f;
#pragma unroll
            for (int k = 0; k < 8; k++) tot += red[k * 64 + qq];
            float inv = 1.f / tot;
            float* ob = outp + ((size_t)(b * 128 + h * 32)) * HW_ + qbase + qq;
#pragma unroll
            for (int u = 0; u < 2; u++) {
                int cc = ci + u * 16;
                float sv = psum[qq * 36 + cc]
                         + psum[2304 + qq * 36 + cc]
                         + psum[4608 + qq * 36 + cc]
                         + psum[6912 + qq * 36 + cc];
                ob[(size_t)cc * HW_] = sv * inv;
            }
        }
    }
}

// ---------------- launch ----------------
extern "C" void kernel_launch(void* const* d_in, const int* in_sizes, int n_in,
                              void* d_out, int out_size)
{
    const float* x     = (const float*)d_in[0];
    const float* w_dw  = (const float*)d_in[1];
    const float* ln_w  = (const float*)d_in[2];
    const float* w_off = (const float*)d_in[3];
    const float* wq    = (const float*)d_in[4];
    const float* wk    = (const float*)d_in[5];
    const float* wv    = (const float*)d_in[6];
    const float* wo    = (const float*)d_in[7];
    const float* rpe   = (const float*)d_in[8];
    float* out = (float*)d_out;

    float *gq, *gao;
    cudaGetSymbolAddress((void**)&gq, g_q);
    cudaGetSymbolAddress((void**)&gao, g_ao);

    cudaFuncSetAttribute(gemm_f16_kernel, cudaFuncAttributeMaxDynamicSharedMemorySize, GH_BYTES);
    cudaFuncSetAttribute(gemm_kv_f16_kernel, cudaFuncAttributeMaxDynamicSharedMemorySize, GH_BYTES);
    cudaFuncSetAttribute(attn_kernel, cudaFuncAttributeMaxDynamicSharedMemorySize,
                         ATTNC_FLOATS * 4);

    // 1: q projection (fp16 mma)
    gemm_f16_kernel<<<128, 1024, GH_BYTES>>>(wq, x, gq, HW_, 16);
    // 2: fused offset pipeline
    offset_kernel<<<64, 1024>>>(x, w_dw, ln_w, w_off);
    // 3: k/v projections (fp16 mma)
    gemm_kv_f16_kernel<<<16, 1024, GH_BYTES>>>(wk, wv);
    // 4: fused attention — persistent, single wave (ncu capture slot)
    attn_kernel<<<NBLK, 1024, ATTNC_FLOATS * 4>>>(rpe, gao);
    // 5: output projection (fp16 mma)
    gemm_f16_kernel<<<128, 1024, GH_BYTES>>>(wo, gao, out, HW_, 16);
}

// round 17
// speedup vs baseline: 1.7940x; 1.0470x over previous
#include <cuda_runtime.h>
#include <cuda_fp16.h>
#include <math.h>
#include <stdint.h>

// ---------------- problem constants ----------------
#define B_   8
#define C_   128
#define HW_  4096
#define NKV_ 256
#define RPE_N 16129     // 127*127

// ---------------- helpers ----------------
__device__ __forceinline__ float ex2f(float x) {
    float r;
    asm("ex2.approx.f32 %0, %1;" : "=f"(r) : "f"(x));
    return r;
}
__device__ __forceinline__ uint32_t h2pack(float lo, float hi) {
    uint32_t r;
    asm("cvt.rn.f16x2.f32 %0, %1, %2;" : "=r"(r) : "f"(hi), "f"(lo));
    return r;
}
__device__ __forceinline__ void mma_f16(float d[4],
    uint32_t a0, uint32_t a1, uint32_t a2, uint32_t a3,
    uint32_t b0, uint32_t b1)
{
    asm volatile(
        "mma.sync.aligned.m16n8k16.row.col.f32.f16.f16.f32 "
        "{%0,%1,%2,%3}, {%4,%5,%6,%7}, {%8,%9}, {%0,%1,%2,%3};"
        : "+f"(d[0]), "+f"(d[1]), "+f"(d[2]), "+f"(d[3])
        : "r"(a0), "r"(a1), "r"(a2), "r"(a3), "r"(b0), "r"(b1));
}
#define FU(x) __float_as_uint(x)

// ---------------- device scratch ----------------
__device__ float g_q  [B_ * C_ * HW_];
__device__ float g_ao [B_ * C_ * HW_];
__device__ float g_pos[16 * NKV_ * 2];
__device__ float g_xs [B_ * C_ * NKV_];
__device__ float g_k  [B_ * C_ * NKV_];
__device__ float g_v  [B_ * C_ * NKV_];

// ---------------- fp16 mma GEMM with float4 staging ----------------
#define GH_U32_A 8704     // 128 * 68
#define GH_U32_B 16896    // 64 * 264
#define GH_BYTES ((GH_U32_A + GH_U32_B) * 4)   // 102400 B

__device__ __forceinline__ void gemm_f16_tile(
    const float* __restrict__ A, const float* __restrict__ Xb,
    float* __restrict__ Yb, int ld)
{
    extern __shared__ float sm[];
    uint32_t* ah = (uint32_t*)sm;
    uint32_t* bhh = ah + GH_U32_A;
    int tid = threadIdx.x;

    // A staging: 2 iters x 2 LDG.128 -> uint4 STS
    for (int i = tid; i < 2048; i += 1024) {
        int m = i >> 4, kp4 = (i & 15) * 4;     // pairs kp4..kp4+3 = cols 2kp4..2kp4+7
        float4 a0 = *(const float4*)(A + m * 128 + 2 * kp4);
        float4 a1 = *(const float4*)(A + m * 128 + 2 * kp4 + 4);
        uint4 u = make_uint4(h2pack(a0.x, a0.y), h2pack(a0.z, a0.w),
                             h2pack(a1.x, a1.y), h2pack(a1.z, a1.w));
        *(uint4*)(ah + m * 68 + kp4) = u;
    }
    // B staging: 4 iters x 2 LDG.128 -> uint4 STS
    for (int i = tid; i < 4096; i += 1024) {
        int kp = i >> 6, n4 = (i & 63) * 4;
        float4 r0 = *(const float4*)(Xb + (size_t)(2 * kp) * ld + n4);
        float4 r1 = *(const float4*)(Xb + (size_t)(2 * kp + 1) * ld + n4);
        uint4 u = make_uint4(h2pack(r0.x, r1.x), h2pack(r0.y, r1.y),
                             h2pack(r0.z, r1.z), h2pack(r0.w, r1.w));
        *(uint4*)(bhh + kp * 264 + n4) = u;
    }
    __syncthreads();

    int lane = tid & 31, w = tid >> 5;
    int r4 = lane >> 2, c4 = lane & 3;
    int mt = (w >> 3) * 32;
    int nt = (w & 7) * 32;

    float d[2][4][4];
#pragma unroll
    for (int s = 0; s < 2; s++)
#pragma unroll
        for (int nb = 0; nb < 4; nb++)
#pragma unroll
            for (int j = 0; j < 4; j++) d[s][nb][j] = 0.f;

#pragma unroll
    for (int ks = 0; ks < 8; ks++) {
        int kp = ks * 8;
        uint32_t a[2][4];
#pragma unroll
        for (int s = 0; s < 2; s++) {
            int qa = mt + s * 16 + r4;
            a[s][0] = ah[qa * 68 + kp + c4];
            a[s][1] = ah[(qa + 8) * 68 + kp + c4];
            a[s][2] = ah[qa * 68 + kp + c4 + 4];
            a[s][3] = ah[(qa + 8) * 68 + kp + c4 + 4];
        }
#pragma unroll
        for (int nb = 0; nb < 4; nb++) {
            int ncol = nt + nb * 8 + r4;
            uint32_t b0 = bhh[(kp + c4) * 264 + ncol];
            uint32_t b1 = bhh[(kp + c4 + 4) * 264 + ncol];
            mma_f16(d[0][nb], a[0][0], a[0][1], a[0][2], a[0][3], b0, b1);
            mma_f16(d[1][nb], a[1][0], a[1][1], a[1][2], a[1][3], b0, b1);
        }
    }
#pragma unroll
    for (int s = 0; s < 2; s++)
#pragma unroll
        for (int nb = 0; nb < 4; nb++) {
            int m0 = mt + s * 16 + r4;
            int n0 = nt + nb * 8 + 2 * c4;
            *(float2*)(Yb + (size_t)m0 * ld + n0)       = make_float2(d[s][nb][0], d[s][nb][1]);
            *(float2*)(Yb + (size_t)(m0 + 8) * ld + n0) = make_float2(d[s][nb][2], d[s][nb][3]);
        }
}

__global__ void __launch_bounds__(1024) gemm_f16_kernel(
    const float* __restrict__ A, const float* __restrict__ X,
    float* __restrict__ Y, int ld, int ntiles)
{
    int b  = blockIdx.x / ntiles;
    int pb = (blockIdx.x % ntiles) * 256;
    gemm_f16_tile(A, X + (size_t)b * 128 * ld + pb, Y + (size_t)b * 128 * ld + pb, ld);
}

__global__ void __launch_bounds__(1024) gemm_kv_f16_kernel(
    const float* __restrict__ wk, const float* __restrict__ wv)
{
    int sel = blockIdx.x >> 3;
    int b   = blockIdx.x & 7;
    const float* A = sel ? wv : wk;
    float* Y = sel ? g_v : g_k;
    gemm_f16_tile(A, g_xs + (size_t)b * 128 * NKV_, Y + (size_t)b * 128 * NKV_, NKV_);
}

// ---------------- fused offset pipeline v2: smem-staged dwconv ----------------
// dynamic smem: stage buffer [16 ch][17 rows][68] floats = 18496 floats (73984 B)
#define OFF_STAGE_FLOATS (16 * 17 * 68)

__global__ void __launch_bounds__(1024) offset_kernel(
    const float* __restrict__ x, const float* __restrict__ w_dw,
    const float* __restrict__ ln_w, const float* __restrict__ w_off)
{
    extern __shared__ float dyn[];          // stage buffer
    __shared__ float off_sm[64 * 65];
    __shared__ float ws_sm[1600];
    __shared__ float pos_y[64], pos_x[64], dm_sm[64];

    int tid = threadIdx.x;
    int bg  = blockIdx.x >> 2;
    int qtr = blockIdx.x & 3;
    int b = bg >> 1, g = bg & 1;

    for (int i = tid; i < 1600; i += 1024) ws_sm[i] = w_dw[i];

    int ybase = 16 * qtr - 2;
    int f4idx = tid & 15;

    // 4 stages of 16 channels
    for (int s = 0; s < 4; s++) {
        int ch0 = s * 16;
        __syncthreads();    // dyn reuse from previous stage (and ws ready on s=0)
        // load 16 ch x 17 rows x 16 float4 (zero-fill OOB rows)
        for (int p = tid >> 4; p < 272; p += 64) {
            int ch = p / 17, r = p % 17;
            int y = ybase + r;
            float4 v = make_float4(0.f, 0.f, 0.f, 0.f);
            if ((unsigned)y < 64u) {
                const float* plane = g_q + ((size_t)(b * 128 + g * 64 + ch0 + ch)) * HW_;
                v = *(const float4*)(plane + y * 64 + f4idx * 4);
            }
            ((float4*)dyn)[ch * 289 + r * 17 + f4idx] = v;
        }
        __syncthreads();
        // conv: thread = (ch of 16, spl of 64)
        {
            int ch = tid >> 6, spl = tid & 63;
            int ry0 = 4 * (spl >> 4);
            int x0 = 4 * (spl & 15) - 2;
            const float* ws = ws_sm + (ch0 + ch) * 25;
            const float* st = dyn + ch * 1156;
            float acc = 0.f;
#pragma unroll
            for (int u = 0; u < 5; u++) {
                const float* row = st + (ry0 + u) * 68;
#pragma unroll
                for (int v = 0; v < 5; v++) {
                    int xx = x0 + v;
                    if ((unsigned)xx < 64u) acc += row[xx] * ws[u * 5 + v];
                }
            }
            off_sm[(ch0 + ch) * 65 + spl] = acc;
        }
    }
    __syncthreads();

    if (tid < 64) {
        int spl = tid;
        int sp = qtr * 64 + spl;
        float s = 0.f, s2 = 0.f;
#pragma unroll 8
        for (int c = 0; c < 64; c++) {
            float t = off_sm[c * 65 + spl];
            s += t; s2 += t * t;
        }
        float mean = s * (1.f / 64.f);
        float var  = s2 * (1.f / 64.f) - mean * mean;
        float rstd = rsqrtf(var + 1e-5f);
        float o0 = 0.f, o1 = 0.f, o2 = 0.f;
#pragma unroll 8
        for (int c = 0; c < 64; c++) {
            float t = off_sm[c * 65 + spl] * rstd * __ldg(&ln_w[c]);
            float ge = 0.5f * t * (1.f + erff(t * 0.70710678118654752f));
            o0 += __ldg(&w_off[c]) * ge;
            o1 += __ldg(&w_off[64 + c]) * ge;
            o2 += __ldg(&w_off[128 + c]) * ge;
        }
        int i = sp >> 4, j = sp & 15;
        float ry = (float)(2 * i + 1) * (1.f / 16.f) - 1.f;
        float rx = (float)(2 * j + 1) * (1.f / 16.f) - 1.f;
        float py = tanhf(o0) * (1.f / 16.f) + ry;
        float px = tanhf(o1) * (1.f / 16.f) + rx;
        pos_y[spl] = py;
        pos_x[spl] = px;
        dm_sm[spl] = 1.f / (1.f + expf(-o2));
        g_pos[bg * 512 + sp * 2]     = py;
        g_pos[bg * 512 + sp * 2 + 1] = px;
    }
    __syncthreads();

    for (int r = tid; r < 4096; r += 1024) {
        int c = r >> 6, spl = r & 63;
        int n = qtr * 64 + spl;
        const float* plane = x + ((size_t)(b * 128 + g * 64 + c)) * HW_;
        float gx = fminf((pos_x[spl] + 1.f) * 31.5f, 62.99999f);
        float gy = fminf((pos_y[spl] + 1.f) * 31.5f, 62.99999f);
        float x0f = floorf(gx), y0f = floorf(gy);
        float wx = gx - x0f, wy = gy - y0f;
        int ix0 = (int)x0f, iy0 = (int)y0f;
        const float* row0 = plane + iy0 * 64 + ix0;
        float v00 = row0[0], v01 = row0[1];
        float v10 = row0[64], v11 = row0[65];
        float top = v00 + (v01 - v00) * wx;
        float bot = v10 + (v11 - v10) * wx;
        float val = top + (bot - top) * wy;
        g_xs[((size_t)(b * 128 + g * 64 + c)) * NKV_ + n] = val * dm_sm[spl];
    }
}

// ---------------- fused attention v14 (unchanged from R16) ----------------
#define SMC_RPE  0
#define SMC_KH   16132
#define SMC_VH   (SMC_KH + 5120)
#define SMC_PTH  (SMC_VH + 4224)
#define SMC_GTB  (SMC_PTH + 8448)
#define SMC_RED  (SMC_GTB + 1024)
#define SMC_QH   (SMC_RED + 512)
#define SMC_PS   (SMC_QH + 1280)
#define ATTNC_FLOATS (SMC_PS + 9216)      // 45956 floats = 183824 B

#define LOG2E_ 1.4426950408889634f
#define NTILES_TOTAL 2048
#define NBLK 148

__device__ __forceinline__ float bilin2h(const uint32_t* __restrict__ rpe_h2,
                                         float gx, float wy0, float wy1,
                                         int r0, int r1)
{
    float x0f = floorf(gx);
    float wx = gx - x0f;
    int ix0 = (int)x0f;
    float2 v0 = __half22float2(*(const __half2*)&rpe_h2[r0 + ix0]);
    float2 v1 = __half22float2(*(const __half2*)&rpe_h2[r1 + ix0]);
    float t0 = v0.x + (v0.y - v0.x) * wx;
    float t1 = v1.x + (v1.y - v1.x) * wx;
    return t0 * wy0 + t1 * wy1;
}

__global__ void __launch_bounds__(1024) attn_kernel(const float* __restrict__ rpe,
                                                    float* __restrict__ outp)
{
    extern __shared__ float sm[];
    uint32_t* rpe_h2 = (uint32_t*)(sm + SMC_RPE);
    uint32_t* kh  = (uint32_t*)(sm + SMC_KH);
    uint32_t* vh  = (uint32_t*)(sm + SMC_VH);
    uint32_t* pth = (uint32_t*)(sm + SMC_PTH);
    float4* gtb   = (float4*)(sm + SMC_GTB);
    float* red    = sm + SMC_RED;
    uint32_t* qh  = (uint32_t*)(sm + SMC_QH);
    float* psum   = sm + SMC_PS;

    int tid = threadIdx.x;
    int lane = tid & 31, w = tid >> 5;
    int r4 = lane >> 2, c4 = lane & 3;
    int mblk = w & 3;
    int ngrp = w >> 2;
    int pvt = w & 7, kq = w >> 3;
    int qm  = (pvt & 3) * 16;
    int cv0 = (pvt >> 2) * 16;

    const float scale2 = 0.17677669529663687f * LOG2E_;

    int tstart = (int)(((long long)blockIdx.x * NTILES_TOTAL) / NBLK);
    int tend   = (int)(((long long)(blockIdx.x + 1) * NTILES_TOTAL) / NBLK);

    int cur_bh = -1;
    int b = 0, h = 0, g = 0;
    float ppy = 0.f, ppx = 0.f;

    for (int tg = tstart; tg < tend; tg++) {
        int bh   = tg >> 6;
        int tile = tg & 63;
        int qbase = tile * 64;

        if (bh != cur_bh) {
            cur_bh = bh;
            b = bh >> 2; h = bh & 3; g = h >> 1;

            const float* rp = rpe + (size_t)h * RPE_N;
            for (int i = tid; i < RPE_N; i += 1024) {
                float cur = rp[i] * LOG2E_;
                float nxt = (i + 1 < RPE_N) ? rp[i + 1] * LOG2E_ : 0.f;
                rpe_h2[i] = h2pack(cur, nxt);
            }
            const float* kb = g_k + ((size_t)(b * 128 + h * 32)) * NKV_;
            for (int i = tid; i < 4096; i += 1024) {
                int cp = i >> 8, n = i & 255;
                kh[n * 20 + cp] = h2pack(kb[(2 * cp) * 256 + n], kb[(2 * cp + 1) * 256 + n]);
            }
            const float* vb = g_v + ((size_t)(b * 128 + h * 32)) * NKV_;
            for (int i = tid; i < 4096; i += 1024) {
                int c = i >> 7, np = i & 127;
                float2 v2 = *(const float2*)&vb[c * 256 + 2 * np];
                vh[c * 132 + np] = h2pack(v2.x, v2.y);
            }
            if (tid < 256) {
                float2 p2 = ((const float2*)(g_pos + (size_t)(b * 2 + g) * 512))[tid];
                ppy = p2.x; ppx = p2.y;
            }
        }

        if (tid < 256) {
            float qy315 = (float)(2 * tile + 1) * 0.4921875f - 31.5f;
            float gy = qy315 + 63.f - 31.5f * ppy;
            float bx = 63.f - 31.5f * ppx;
            float y0f = floorf(gy);
            float wy = gy - y0f;
            unsigned r0 = (unsigned)((int)y0f * 127);
            gtb[tid] = make_float4(bx, 1.f - wy, wy, __uint_as_float(r0 | ((r0 + 127) << 16)));
        }
        {
            int cp = tid >> 6, qi = tid & 63;
            const float* qb = g_q + ((size_t)(b * 128 + h * 32)) * HW_ + qbase;
            float v0 = qb[(size_t)(2 * cp) * HW_ + qi] * scale2;
            float v1 = qb[(size_t)(2 * cp + 1) * HW_ + qi] * scale2;
            qh[qi * 20 + cp] = h2pack(v0, v1);
        }
        __syncthreads();

        // ---- QK via f16 mma ----
        float d[4][4];
#pragma unroll
        for (int i = 0; i < 4; i++)
#pragma unroll
            for (int j = 0; j < 4; j++) d[i][j] = 0.f;

        int qa = mblk * 16 + r4;
#pragma unroll
        for (int ks = 0; ks < 2; ks++) {
            int kp = ks * 8;
            uint32_t a0 = qh[qa * 20 + kp + c4];
            uint32_t a1 = qh[(qa + 8) * 20 + kp + c4];
            uint32_t a2 = qh[qa * 20 + kp + c4 + 4];
            uint32_t a3 = qh[(qa + 8) * 20 + kp + c4 + 4];
#pragma unroll
            for (int nb = 0; nb < 4; nb++) {
                int ncol = ngrp * 32 + nb * 8 + r4;
                uint32_t b0 = kh[ncol * 20 + kp + c4];
                uint32_t b1 = kh[ncol * 20 + kp + c4 + 4];
                mma_f16(d[nb], a0, a1, a2, a3, b0, b1);
            }
        }

        // ---- fused bias + exp2 + half2 store + partial sums ----
        {
            float axl = (float)(2 * (mblk * 16 + r4) + 1) * 0.4921875f - 31.5f;
            float axh = axl + 7.875f;
            float suml = 0.f, sumh = 0.f;
            int qrow = mblk * 16 + r4;
#pragma unroll
            for (int nb = 0; nb < 4; nb++) {
                int nn = ngrp * 32 + nb * 8 + 2 * c4;
                float4 G0 = gtb[nn], G1 = gtb[nn + 1];
                uint32_t u0 = __float_as_uint(G0.w);
                uint32_t u1 = __float_as_uint(G1.w);
                int r00 = u0 & 0xffff, r01 = u0 >> 16;
                int r10 = u1 & 0xffff, r11 = u1 >> 16;
                float e0 = ex2f(d[nb][0] + bilin2h(rpe_h2, axl + G0.x, G0.y, G0.z, r00, r01));
                float e1 = ex2f(d[nb][1] + bilin2h(rpe_h2, axl + G1.x, G1.y, G1.z, r10, r11));
                float e2 = ex2f(d[nb][2] + bilin2h(rpe_h2, axh + G0.x, G0.y, G0.z, r00, r01));
                float e3 = ex2f(d[nb][3] + bilin2h(rpe_h2, axh + G1.x, G1.y, G1.z, r10, r11));
                suml += e0 + e1;
                sumh += e2 + e3;
                int npi = (nn >> 1);
                pth[qrow * 132 + npi]       = h2pack(e0, e1);
                pth[(qrow + 8) * 132 + npi] = h2pack(e2, e3);
            }
            suml += __shfl_xor_sync(0xffffffffu, suml, 1);
            suml += __shfl_xor_sync(0xffffffffu, suml, 2);
            sumh += __shfl_xor_sync(0xffffffffu, sumh, 1);
            sumh += __shfl_xor_sync(0xffffffffu, sumh, 2);
            if (c4 == 0) {
                red[ngrp * 64 + qrow]     = suml;
                red[ngrp * 64 + qrow + 8] = sumh;
            }
        }
        __syncthreads();

        // ---- PV via f16 mma ----
        float dd0[4] = {0.f, 0.f, 0.f, 0.f};
        float dd1[4] = {0.f, 0.f, 0.f, 0.f};
#pragma unroll
        for (int ks = 0; ks < 4; ks++) {
            int koff = kq * 32 + ks * 8;
            uint32_t a0 = pth[(qm + r4) * 132 + koff + c4];
            uint32_t a1 = pth[(qm + 8 + r4) * 132 + koff + c4];
            uint32_t a2 = pth[(qm + r4) * 132 + koff + c4 + 4];
            uint32_t a3 = pth[(qm + 8 + r4) * 132 + koff + c4 + 4];
            uint32_t b0 = vh[(cv0 + r4) * 132 + koff + c4];
            uint32_t b1 = vh[(cv0 + r4) * 132 + koff + c4 + 4];
            uint32_t b2 = vh[(cv0 + 8 + r4) * 132 + koff + c4];
            uint32_t b3 = vh[(cv0 + 8 + r4) * 132 + koff + c4 + 4];
            mma_f16(dd0, a0, a1, a2, a3, b0, b1);
            mma_f16(dd1, a0, a1, a2, a3, b2, b3);
        }
        {
            float* ps = psum + kq * 2304;
            *(float2*)&ps[(qm + r4) * 36 + cv0 + 2 * c4]         = make_float2(dd0[0], dd0[1]);
            *(float2*)&ps[(qm + 8 + r4) * 36 + cv0 + 2 * c4]     = make_float2(dd0[2], dd0[3]);
            *(float2*)&ps[(qm + r4) * 36 + cv0 + 8 + 2 * c4]     = make_float2(dd1[0], dd1[1]);
            *(float2*)&ps[(qm + 8 + r4) * 36 + cv0 + 8 + 2 * c4] = make_float2(dd1[2], dd1[3]);
        }
        __syncthreads();

        // ---- epilogue ----
        {
            int qq = tid & 63;
            int ci = tid >> 6;
            float tot = 0.f;
#pragma unroll
            for (int k = 0; k < 8; k++) tot += red[k * 64 + qq];
            float inv = 1.f / tot;
            float* ob = outp + ((size_t)(b * 128 + h * 32)) * HW_ + qbase + qq;
#pragma unroll
            for (int u = 0; u < 2; u++) {
                int cc = ci + u * 16;
                float sv = psum[qq * 36 + cc]
                         + psum[2304 + qq * 36 + cc]
                         + psum[4608 + qq * 36 + cc]
                         + psum[6912 + qq * 36 + cc];
                ob[(size_t)cc * HW_] = sv * inv;
            }
        }
    }
}

// ---------------- launch ----------------
extern "C" void kernel_launch(void* const* d_in, const int* in_sizes, int n_in,
                              void* d_out, int out_size)
{
    const float* x     = (const float*)d_in[0];
    const float* w_dw  = (const float*)d_in[1];
    const float* ln_w  = (const float*)d_in[2];
    const float* w_off = (const float*)d_in[3];
    const float* wq    = (const float*)d_in[4];
    const float* wk    = (const float*)d_in[5];
    const float* wv    = (const float*)d_in[6];
    const float* wo    = (const float*)d_in[7];
    const float* rpe   = (const float*)d_in[8];
    float* out = (float*)d_out;

    float *gq, *gao;
    cudaGetSymbolAddress((void**)&gq, g_q);
    cudaGetSymbolAddress((void**)&gao, g_ao);

    cudaFuncSetAttribute(gemm_f16_kernel, cudaFuncAttributeMaxDynamicSharedMemorySize, GH_BYTES);
    cudaFuncSetAttribute(gemm_kv_f16_kernel, cudaFuncAttributeMaxDynamicSharedMemorySize, GH_BYTES);
    cudaFuncSetAttribute(offset_kernel, cudaFuncAttributeMaxDynamicSharedMemorySize,
                         OFF_STAGE_FLOATS * 4);
    cudaFuncSetAttribute(attn_kernel, cudaFuncAttributeMaxDynamicSharedMemorySize,
                         ATTNC_FLOATS * 4);

    // 1: q projection (fp16 mma, float4 staging)
    gemm_f16_kernel<<<128, 1024, GH_BYTES>>>(wq, x, gq, HW_, 16);
    // 2: fused offset pipeline (smem-staged dwconv)
    offset_kernel<<<64, 1024, OFF_STAGE_FLOATS * 4>>>(x, w_dw, ln_w, w_off);
    // 3: k/v projections
    gemm_kv_f16_kernel<<<16, 1024, GH_BYTES>>>(wk, wv);
    // 4: fused attention — persistent, single wave (ncu capture slot)
    attn_kernel<<<NBLK, 1024, ATTNC_FLOATS * 4>>>(rpe, gao);
    // 5: output projection
    gemm_f16_kernel<<<128, 1024, GH_BYTES>>>(wo, gao, out, HW_, 16);
}